// round 2
// baseline (speedup 1.0000x reference)
#include <cuda_runtime.h>
#include <cuda_bf16.h>
#include <math.h>

#define B 4
#define A_TOTAL 159882
#define KCAND 4507
#define POST_NMS 1000
#define SORT_N 8192

__constant__ int c_lvl_n[5]   = {120000, 30000, 7500, 1875, 507};
__constant__ int c_lvl_off[5] = {0, 120000, 150000, 157500, 159375};
__constant__ int c_lvl_k[5]   = {1000, 1000, 1000, 1000, 507};

// static scratch (no allocation allowed)
__device__ unsigned long long d_topk_key[B * 5][1024];
__device__ float              d_cand_box[B][KCAND][4];
__device__ float              d_cand_sig[B][KCAND];
__device__ unsigned char      d_cand_valid[B][KCAND];
__device__ unsigned long long d_sortkey[B][KCAND];
__device__ unsigned int       d_sorted_pos[B][KCAND];
__device__ unsigned char      d_keep[B][KCAND];

// monotone float -> u32 (ascending), then inverted for descending sort keys
__device__ __forceinline__ unsigned int fkey_desc(float f) {
    unsigned int b = __float_as_uint(f);
    unsigned int o = (b & 0x80000000u) ? ~b : (b | 0x80000000u);
    return ~o;
}

// ---------------------------------------------------------------------------
// K1: per-(batch,level) exact top-k via MSB-first radix select on 64-bit keys
//     key = (~ord(logit)) << 32 | idx   -> k smallest = top-k (value desc, idx asc)
// ---------------------------------------------------------------------------
__global__ void k_topk(const float* __restrict__ obj) {
    const int blk = blockIdx.x;
    const int b = blk / 5, l = blk % 5;
    const int n = c_lvl_n[l], off = c_lvl_off[l], k = c_lvl_k[l];
    const float* row = obj + (size_t)b * A_TOTAL + off;

    __shared__ unsigned int hist[256];
    __shared__ unsigned long long sh_prefix;
    __shared__ unsigned int sh_kk;
    __shared__ int sh_cnt;
    __shared__ unsigned long long skey[1024];

    unsigned long long T;
    if (k >= n) {
        T = ~0ULL;
    } else {
        if (threadIdx.x == 0) { sh_prefix = 0ULL; sh_kk = (unsigned)k; }
        __syncthreads();
        for (int byte = 7; byte >= 0; --byte) {
            for (int i = threadIdx.x; i < 256; i += blockDim.x) hist[i] = 0;
            __syncthreads();
            const unsigned long long prefix = sh_prefix;
            const unsigned long long mask_hi = (byte == 7) ? 0ULL : (~0ULL << ((byte + 1) * 8));
            const int shift = byte * 8;
            for (int i = threadIdx.x; i < n; i += blockDim.x) {
                unsigned long long key =
                    ((unsigned long long)fkey_desc(row[i]) << 32) | (unsigned int)i;
                if ((key & mask_hi) == prefix)
                    atomicAdd(&hist[(unsigned int)(key >> shift) & 0xFFu], 1u);
            }
            __syncthreads();
            if (threadIdx.x < 32) {
                const unsigned int lane = threadIdx.x;
                unsigned int cnt[8], tot = 0;
#pragma unroll
                for (int t = 0; t < 8; t++) { cnt[t] = hist[lane * 8 + t]; tot += cnt[t]; }
                unsigned int x = tot;
#pragma unroll
                for (int d = 1; d < 32; d <<= 1) {
                    unsigned int y = __shfl_up_sync(0xffffffffu, x, d);
                    if (lane >= d) x += y;
                }
                const unsigned int incl = x, excl = x - tot;
                const unsigned int kk = sh_kk;
                if (excl < kk && kk <= incl) {
                    unsigned int c = excl;
                    int sel = -1;
#pragma unroll
                    for (int t = 0; t < 8; t++) {
                        if (sel < 0) {
                            if (c + cnt[t] >= kk) sel = t;
                            else c += cnt[t];
                        }
                    }
                    sh_kk = kk - c;
                    sh_prefix = sh_prefix | ((unsigned long long)(lane * 8 + sel) << shift);
                }
            }
            __syncthreads();
        }
        T = sh_prefix;
    }

    // compact the k keys <= T (keys unique => exactly k)
    for (int i = threadIdx.x; i < 1024; i += blockDim.x) skey[i] = ~0ULL;
    if (threadIdx.x == 0) sh_cnt = 0;
    __syncthreads();
    for (int i = threadIdx.x; i < n; i += blockDim.x) {
        unsigned long long key = ((unsigned long long)fkey_desc(row[i]) << 32) | (unsigned int)i;
        if (key <= T) {
            int p = atomicAdd(&sh_cnt, 1);
            skey[p] = key;
        }
    }
    __syncthreads();

    // bitonic sort 1024 ascending (=> logit desc, idx asc)
    for (int size = 2; size <= 1024; size <<= 1) {
        for (int stride = size >> 1; stride > 0; stride >>= 1) {
            const int t = threadIdx.x;
            const int p = t ^ stride;
            if (p > t) {
                const bool asc = ((t & size) == 0);
                unsigned long long a = skey[t], bb = skey[p];
                if (asc ? (a > bb) : (a < bb)) { skey[t] = bb; skey[p] = a; }
            }
            __syncthreads();
        }
    }
    d_topk_key[blk][threadIdx.x] = skey[threadIdx.x];
}

// ---------------------------------------------------------------------------
// K2: decode + sigmoid + clip + valid + global-sort key, per selected candidate
// ---------------------------------------------------------------------------
__global__ void k_decode(const float* __restrict__ obj,
                         const float* __restrict__ deltas,
                         const float* __restrict__ anchors) {
    const int g = blockIdx.x * blockDim.x + threadIdx.x;
    if (g >= B * KCAND) return;
    const int b = g / KCAND;
    const int pos = g - b * KCAND;
    const int l = pos / 1000;                 // cand layout: 1000,1000,1000,1000,507
    const int r = pos - l * 1000;

    const unsigned long long key = d_topk_key[b * 5 + l][r];
    const unsigned int idx = (unsigned int)key;
    const int a = c_lvl_off[l] + (int)idx;

    const float logit = obj[(size_t)b * A_TOTAL + a];

    const float4 an = *(const float4*)(anchors + (size_t)a * 4);
    const float4 dl = *(const float4*)(deltas + ((size_t)b * A_TOTAL + a) * 4);

    const float BBOX_CLIP = (float)4.135166556742356;

    const float wa = __fsub_rn(an.z, an.x);
    const float ha = __fsub_rn(an.w, an.y);
    const float cxa = __fadd_rn(an.x, __fmul_rn(0.5f, wa));
    const float cya = __fadd_rn(an.y, __fmul_rn(0.5f, ha));

    const float dx = dl.x, dy = dl.y;
    const float dw = fminf(dl.z, BBOX_CLIP);
    const float dh = fminf(dl.w, BBOX_CLIP);

    const float cx = __fadd_rn(__fmul_rn(dx, wa), cxa);
    const float cy = __fadd_rn(__fmul_rn(dy, ha), cya);
    const float w = __fmul_rn(expf(dw), wa);
    const float h = __fmul_rn(expf(dh), ha);

    const float hw = __fmul_rn(0.5f, w);
    const float hh = __fmul_rn(0.5f, h);
    float x1 = __fsub_rn(cx, hw);
    float y1 = __fsub_rn(cy, hh);
    float x2 = __fadd_rn(cx, hw);
    float y2 = __fadd_rn(cy, hh);

    x1 = fminf(fmaxf(x1, 0.0f), 800.0f);
    y1 = fminf(fmaxf(y1, 0.0f), 800.0f);
    x2 = fminf(fmaxf(x2, 0.0f), 800.0f);
    y2 = fminf(fmaxf(y2, 0.0f), 800.0f);

    // sigmoid = 1 / (1 + exp(-x))   (XLA LogisticExpander)
    const float sig = __fdiv_rn(1.0f, __fadd_rn(1.0f, expf(-logit)));

    const bool valid = (__fsub_rn(x2, x1) >= 0.001f) &&
                       (__fsub_rn(y2, y1) >= 0.001f) &&
                       (sig >= 0.0f);

    d_cand_box[b][pos][0] = x1;
    d_cand_box[b][pos][1] = y1;
    d_cand_box[b][pos][2] = x2;
    d_cand_box[b][pos][3] = y2;
    d_cand_sig[b][pos] = sig;
    d_cand_valid[b][pos] = valid ? 1 : 0;

    const float sigp = valid ? sig : __int_as_float(0xff800000); // -inf
    d_sortkey[b][pos] = ((unsigned long long)fkey_desc(sigp) << 32) | (unsigned int)pos;
}

// ---------------------------------------------------------------------------
// K3: per-batch stable sort (score desc, candpos asc) via bitonic on 8192 keys
// ---------------------------------------------------------------------------
extern __shared__ unsigned long long s_sort[];
__global__ void k_sort() {
    const int b = blockIdx.x;
    for (int i = threadIdx.x; i < SORT_N; i += blockDim.x)
        s_sort[i] = (i < KCAND) ? d_sortkey[b][i] : ~0ULL;
    __syncthreads();
    for (int size = 2; size <= SORT_N; size <<= 1) {
        for (int stride = size >> 1; stride > 0; stride >>= 1) {
            for (int t = threadIdx.x; t < SORT_N / 2; t += blockDim.x) {
                const int i = ((t / stride) * (stride << 1)) + (t & (stride - 1));
                const int j = i + stride;
                const bool asc = ((i & size) == 0);
                unsigned long long a = s_sort[i], bb = s_sort[j];
                if (asc ? (a > bb) : (a < bb)) { s_sort[i] = bb; s_sort[j] = a; }
            }
            __syncthreads();
        }
    }
    for (int i = threadIdx.x; i < KCAND; i += blockDim.x)
        d_sorted_pos[b][i] = (unsigned int)s_sort[i];
}

// ---------------------------------------------------------------------------
// K4: per-(batch,level) greedy NMS in topk-rank order on offset boxes
//     (cross-level IoU is exactly 0; invalid never suppress)
// ---------------------------------------------------------------------------
__global__ void k_nms() {
    const int blk = blockIdx.x;
    const int b = blk / 5, l = blk % 5;
    const int k = c_lvl_k[l];
    const int cbase = l * 1000;

    __shared__ float sx1[1000], sy1[1000], sx2[1000], sy2[1000], sar[1000];
    __shared__ unsigned char kp[1000];

    const float loff = (float)l * 1000.0f;
    for (int r = threadIdx.x; r < k; r += blockDim.x) {
        const int pos = cbase + r;
        const float ox1 = __fadd_rn(d_cand_box[b][pos][0], loff);
        const float oy1 = __fadd_rn(d_cand_box[b][pos][1], loff);
        const float ox2 = __fadd_rn(d_cand_box[b][pos][2], loff);
        const float oy2 = __fadd_rn(d_cand_box[b][pos][3], loff);
        sx1[r] = ox1; sy1[r] = oy1; sx2[r] = ox2; sy2[r] = oy2;
        sar[r] = __fmul_rn(__fsub_rn(ox2, ox1), __fsub_rn(oy2, oy1));
        kp[r] = d_cand_valid[b][pos];
    }
    __syncthreads();

    const int j = threadIdx.x;
    for (int i = 0; i < k; i++) {
        if (kp[i]) {   // uniform across block (shared value)
            if (j > i && j < k && kp[j]) {
                const float xx1 = fmaxf(sx1[i], sx1[j]);
                const float yy1 = fmaxf(sy1[i], sy1[j]);
                const float xx2 = fminf(sx2[i], sx2[j]);
                const float yy2 = fminf(sy2[i], sy2[j]);
                const float w = fmaxf(__fsub_rn(xx2, xx1), 0.0f);
                const float h = fmaxf(__fsub_rn(yy2, yy1), 0.0f);
                const float inter = __fmul_rn(w, h);
                const float uni = __fsub_rn(__fadd_rn(sar[i], sar[j]), inter);
                const float iou = __fdiv_rn(inter, uni);
                if (iou > 0.7f) kp[j] = 0;
            }
            __syncthreads();
        }
    }

    for (int r = threadIdx.x; r < k; r += blockDim.x)
        d_keep[b][cbase + r] = kp[r];
}

// ---------------------------------------------------------------------------
// K5: per-batch rank assignment (cumsum of keep over sorted order) + output
// ---------------------------------------------------------------------------
__global__ void k_out(float* __restrict__ out) {
    const int b = blockIdx.x;
    float* ob = out + (size_t)b * POST_NMS * 5;
    for (int i = threadIdx.x; i < POST_NMS * 5; i += blockDim.x) ob[i] = 0.0f;
    __syncthreads();

    if (threadIdx.x < 32) {
        const int lane = threadIdx.x;
        int rank = 0;
        for (int base = 0; base < KCAND; base += 32) {
            const int i = base + lane;
            int pos = 0, kpv = 0;
            if (i < KCAND) {
                pos = (int)d_sorted_pos[b][i];
                kpv = d_keep[b][pos];
            }
            const unsigned int mask = __ballot_sync(0xffffffffu, kpv);
            const int myrank = rank + __popc(mask & ((1u << lane) - 1u));
            if (kpv && myrank < POST_NMS) {
                float* row = ob + (size_t)myrank * 5;
                row[0] = d_cand_box[b][pos][0];
                row[1] = d_cand_box[b][pos][1];
                row[2] = d_cand_box[b][pos][2];
                row[3] = d_cand_box[b][pos][3];
                row[4] = d_cand_sig[b][pos];
            }
            rank += __popc(mask);
            if (rank >= POST_NMS) break;
        }
    }
}

// ---------------------------------------------------------------------------
extern "C" void kernel_launch(void* const* d_in, const int* in_sizes, int n_in,
                              void* d_out, int out_size) {
    const float* obj = (const float*)d_in[0];
    const float* deltas = (const float*)d_in[1];
    const float* anchors = (const float*)d_in[2];
    float* out = (float*)d_out;

    k_topk<<<B * 5, 1024>>>(obj);

    const int total = B * KCAND;
    k_decode<<<(total + 255) / 256, 256>>>(obj, deltas, anchors);

    cudaFuncSetAttribute(k_sort, cudaFuncAttributeMaxDynamicSharedMemorySize,
                         SORT_N * sizeof(unsigned long long));
    k_sort<<<B, 1024, SORT_N * sizeof(unsigned long long)>>>();

    k_nms<<<B * 5, 1024>>>();

    k_out<<<B, 256>>>(out);
}

// round 5
// speedup vs baseline: 1.4684x; 1.4684x over previous
#include <cuda_runtime.h>
#include <cuda_bf16.h>
#include <math.h>

#define B 4
#define A_TOTAL 159882
#define KCAND 4507
#define POST_NMS 1000
#define SORT_N 8192

__constant__ int c_lvl_n[5]   = {120000, 30000, 7500, 1875, 507};
__constant__ int c_lvl_off[5] = {0, 120000, 150000, 157500, 159375};
__constant__ int c_lvl_k[5]   = {1000, 1000, 1000, 1000, 507};

// static scratch (no allocation allowed)
__device__ unsigned long long d_topk_key[B * 5][1024];
__device__ float              d_cand_box[B][KCAND][4];
__device__ float              d_cand_sig[B][KCAND];
__device__ unsigned char      d_cand_valid[B][KCAND];
__device__ unsigned long long d_sortkey[B][KCAND];
__device__ unsigned int       d_sorted_pos[B][KCAND];
__device__ unsigned char      d_keep[B][KCAND];

// monotone float -> u32 (ascending), then inverted for descending sort keys
__device__ __forceinline__ unsigned int fkey_desc(float f) {
    unsigned int b = __float_as_uint(f);
    unsigned int o = (b & 0x80000000u) ? ~b : (b | 0x80000000u);
    return ~o;
}

// ---------------------------------------------------------------------------
// K1: per-(batch,level) exact top-k.
//   2048-bin histogram on top-11 bits of the desc key -> threshold bin,
//   compact (lows + bin-ties) -> one 4096 bitonic sort -> first k keys are
//   exactly top-k (value desc, idx asc). 2 full passes over level data.
// ---------------------------------------------------------------------------
__global__ void k_topk(const float* __restrict__ obj) {
    const int blk = blockIdx.x;
    const int b = blk / 5, l = blk % 5;
    const int n = c_lvl_n[l], off = c_lvl_off[l], k = c_lvl_k[l];
    const float* row = obj + (size_t)b * A_TOTAL + off;

    __shared__ unsigned int hist[2048];
    __shared__ unsigned int wsum[32];
    __shared__ int sh_bin;
    __shared__ int cntL, cntT;
    __shared__ unsigned long long skey[4096];

    for (int i = threadIdx.x; i < 2048; i += 1024) hist[i] = 0;
    for (int i = threadIdx.x; i < 4096; i += 1024) skey[i] = ~0ULL;
    if (threadIdx.x == 0) { cntL = 0; cntT = 0; sh_bin = 1 << 29; }
    __syncthreads();

    if (k < n) {
        for (int i = threadIdx.x; i < n; i += 1024)
            atomicAdd(&hist[fkey_desc(row[i]) >> 21], 1u);
        __syncthreads();
        const int wid = threadIdx.x >> 5, lane = threadIdx.x & 31;
        {
            unsigned int s = hist[wid * 64 + lane] + hist[wid * 64 + 32 + lane];
#pragma unroll
            for (int d = 16; d > 0; d >>= 1) s += __shfl_down_sync(0xffffffffu, s, d);
            if (lane == 0) wsum[wid] = s;
        }
        __syncthreads();
        if (threadIdx.x == 0) {
            unsigned int cum = 0; int g = 0;
            while (g < 32 && cum + wsum[g] < (unsigned int)k) { cum += wsum[g]; g++; }
            int bin = g * 64;
            while (cum + hist[bin] < (unsigned int)k) { cum += hist[bin]; bin++; }
            sh_bin = bin;
        }
        __syncthreads();
    }
    const int bin = sh_bin;

    for (int i = threadIdx.x; i < n; i += 1024) {
        const unsigned long long key =
            ((unsigned long long)fkey_desc(row[i]) << 32) | (unsigned int)i;
        const int hb = (int)(key >> 53);
        if (hb < bin) {
            int p = atomicAdd(&cntL, 1);
            if (p < 2048) skey[p] = key;
        } else if (hb == bin) {
            int p = atomicAdd(&cntT, 1);
            if (p < 2048) skey[2048 + p] = key;
        }
    }
    __syncthreads();

    // bitonic sort 4096 ascending (=> logit desc, idx asc)
    for (int size = 2; size <= 4096; size <<= 1) {
        for (int stride = size >> 1; stride > 0; stride >>= 1) {
            for (int t = threadIdx.x; t < 2048; t += 1024) {
                const int i = ((t / stride) * (stride << 1)) + (t & (stride - 1));
                const int j = i + stride;
                const bool asc = ((i & size) == 0);
                unsigned long long a = skey[i], bb = skey[j];
                if (asc ? (a > bb) : (a < bb)) { skey[i] = bb; skey[j] = a; }
            }
            __syncthreads();
        }
    }
    if (threadIdx.x < k) d_topk_key[blk][threadIdx.x] = skey[threadIdx.x];
}

// ---------------------------------------------------------------------------
// K2: decode + sigmoid + clip + valid + global-sort key, per selected candidate
// ---------------------------------------------------------------------------
__global__ void k_decode(const float* __restrict__ obj,
                         const float* __restrict__ deltas,
                         const float* __restrict__ anchors) {
    const int g = blockIdx.x * blockDim.x + threadIdx.x;
    if (g >= B * KCAND) return;
    const int b = g / KCAND;
    const int pos = g - b * KCAND;
    const int l = pos / 1000;                 // cand layout: 1000,1000,1000,1000,507
    const int r = pos - l * 1000;

    const unsigned long long key = d_topk_key[b * 5 + l][r];
    const unsigned int idx = (unsigned int)key;
    const int a = c_lvl_off[l] + (int)idx;

    const float logit = obj[(size_t)b * A_TOTAL + a];

    const float4 an = *(const float4*)(anchors + (size_t)a * 4);
    const float4 dl = *(const float4*)(deltas + ((size_t)b * A_TOTAL + a) * 4);

    const float BBOX_CLIP = (float)4.135166556742356;

    const float wa = __fsub_rn(an.z, an.x);
    const float ha = __fsub_rn(an.w, an.y);
    const float cxa = __fadd_rn(an.x, __fmul_rn(0.5f, wa));
    const float cya = __fadd_rn(an.y, __fmul_rn(0.5f, ha));

    const float dx = dl.x, dy = dl.y;
    const float dw = fminf(dl.z, BBOX_CLIP);
    const float dh = fminf(dl.w, BBOX_CLIP);

    const float cx = __fadd_rn(__fmul_rn(dx, wa), cxa);
    const float cy = __fadd_rn(__fmul_rn(dy, ha), cya);
    const float w = __fmul_rn(expf(dw), wa);
    const float h = __fmul_rn(expf(dh), ha);

    const float hw = __fmul_rn(0.5f, w);
    const float hh = __fmul_rn(0.5f, h);
    float x1 = __fsub_rn(cx, hw);
    float y1 = __fsub_rn(cy, hh);
    float x2 = __fadd_rn(cx, hw);
    float y2 = __fadd_rn(cy, hh);

    x1 = fminf(fmaxf(x1, 0.0f), 800.0f);
    y1 = fminf(fmaxf(y1, 0.0f), 800.0f);
    x2 = fminf(fmaxf(x2, 0.0f), 800.0f);
    y2 = fminf(fmaxf(y2, 0.0f), 800.0f);

    // sigmoid = 1 / (1 + exp(-x))   (XLA LogisticExpander)
    const float sig = __fdiv_rn(1.0f, __fadd_rn(1.0f, expf(-logit)));

    const bool valid = (__fsub_rn(x2, x1) >= 0.001f) &&
                       (__fsub_rn(y2, y1) >= 0.001f) &&
                       (sig >= 0.0f);

    d_cand_box[b][pos][0] = x1;
    d_cand_box[b][pos][1] = y1;
    d_cand_box[b][pos][2] = x2;
    d_cand_box[b][pos][3] = y2;
    d_cand_sig[b][pos] = sig;
    d_cand_valid[b][pos] = valid ? 1 : 0;

    const float sigp = valid ? sig : __int_as_float(0xff800000); // -inf
    d_sortkey[b][pos] = ((unsigned long long)fkey_desc(sigp) << 32) | (unsigned int)pos;
}

// ---------------------------------------------------------------------------
// K3: per-batch stable sort (score desc, candpos asc) via bitonic on 8192 keys
// ---------------------------------------------------------------------------
extern __shared__ unsigned long long s_sort[];
__global__ void k_sort() {
    const int b = blockIdx.x;
    for (int i = threadIdx.x; i < SORT_N; i += blockDim.x)
        s_sort[i] = (i < KCAND) ? d_sortkey[b][i] : ~0ULL;
    __syncthreads();
    for (int size = 2; size <= SORT_N; size <<= 1) {
        for (int stride = size >> 1; stride > 0; stride >>= 1) {
            for (int t = threadIdx.x; t < SORT_N / 2; t += blockDim.x) {
                const int i = ((t / stride) * (stride << 1)) + (t & (stride - 1));
                const int j = i + stride;
                const bool asc = ((i & size) == 0);
                unsigned long long a = s_sort[i], bb = s_sort[j];
                if (asc ? (a > bb) : (a < bb)) { s_sort[i] = bb; s_sort[j] = a; }
            }
            __syncthreads();
        }
    }
    for (int i = threadIdx.x; i < KCAND; i += blockDim.x)
        d_sorted_pos[b][i] = (unsigned int)s_sort[i];
}

// ---------------------------------------------------------------------------
// K4: per-(batch,level) NMS: parallel suppression bitmatrix + warp-serial scan
// dyn smem: mat[1000][16] u64 (128000) | sbox float4[1000] (16000)
//           | sar float[1000] (4000) | ball u32[32] (128) | remw u64[16] (128)
// ---------------------------------------------------------------------------
#define NMS_SMEM (128000 + 16000 + 4000 + 128 + 128)
__global__ void k_nms() {
    extern __shared__ unsigned char dyn[];
    unsigned long long* mat = (unsigned long long*)dyn;                  // [1000][16]
    float4* sbox = (float4*)(dyn + 128000);                              // [1000]
    float*  sar  = (float*)(dyn + 128000 + 16000);                       // [1000]
    unsigned int* ball = (unsigned int*)(dyn + 128000 + 16000 + 4000);   // [32]
    unsigned long long* remw =
        (unsigned long long*)(dyn + 128000 + 16000 + 4000 + 128);        // [16]

    const int blk = blockIdx.x;
    const int b = blk / 5, l = blk % 5;
    const int k = c_lvl_k[l];
    const int cbase = l * 1000;
    const int tid = threadIdx.x;
    const float loff = (float)l * 1000.0f;

    int valid_flag = 0;
    if (tid < k) {
        const int pos = cbase + tid;
        const float ox1 = __fadd_rn(d_cand_box[b][pos][0], loff);
        const float oy1 = __fadd_rn(d_cand_box[b][pos][1], loff);
        const float ox2 = __fadd_rn(d_cand_box[b][pos][2], loff);
        const float oy2 = __fadd_rn(d_cand_box[b][pos][3], loff);
        sbox[tid] = make_float4(ox1, oy1, ox2, oy2);
        sar[tid] = __fmul_rn(__fsub_rn(ox2, ox1), __fsub_rn(oy2, oy1));
        valid_flag = d_cand_valid[b][pos];
    }
    const unsigned int bal = __ballot_sync(0xffffffffu, valid_flag);
    if ((tid & 31) == 0) ball[tid >> 5] = bal;
    __syncthreads();

    const int nw = (k + 63) >> 6;

    // build suppression matrix: row i, bit j set iff j>i and iou(i,j) > 0.7
    if (tid < k) {
        const float4 bi = sbox[tid];
        const float ai = sar[tid];
        const int w0 = (tid + 1) >> 6;
        for (int w = 0; w < w0; w++) mat[tid * 16 + w] = 0ULL;
        for (int w = w0; w < nw; w++) {
            unsigned long long bits = 0ULL;
            const int jb = w << 6;
            const int jend = min(64, k - jb);
            for (int jo = 0; jo < jend; jo++) {
                const int j = jb + jo;
                if (j > tid) {
                    const float4 bj = sbox[j];
                    const float xx1 = fmaxf(bi.x, bj.x);
                    const float yy1 = fmaxf(bi.y, bj.y);
                    const float xx2 = fminf(bi.z, bj.z);
                    const float yy2 = fminf(bi.w, bj.w);
                    const float ww = fmaxf(__fsub_rn(xx2, xx1), 0.0f);
                    const float hh = fmaxf(__fsub_rn(yy2, yy1), 0.0f);
                    const float inter = __fmul_rn(ww, hh);
                    const float uni = __fsub_rn(__fadd_rn(ai, sar[j]), inter);
                    const float iou = __fdiv_rn(inter, uni);
                    if (iou > 0.7f) bits |= 1ULL << jo;
                }
            }
            mat[tid * 16 + w] = bits;
        }
    }
    __syncthreads();

    // warp 0: greedy scan. removed starts as ~valid; kept i ORs its row.
    if (tid < 32) {
        unsigned long long removed = ~0ULL;
        if (tid < nw) {
            const unsigned long long lo = ball[tid * 2];
            const unsigned long long hi = ball[tid * 2 + 1];
            removed = ~(lo | (hi << 32));
        }
        unsigned long long done = 0ULL;
        for (int w = 0; w < nw; w++) {
            while (true) {
                const unsigned long long rw = __shfl_sync(0xffffffffu, removed, w);
                const unsigned long long dn = __shfl_sync(0xffffffffu, done, w);
                const unsigned long long live = ~rw & ~dn;
                if (!live) break;
                const int bit = __ffsll((long long)live) - 1;
                const int i = (w << 6) + bit;
                if (tid == w) done |= 1ULL << bit;
                if (tid < 16) removed |= mat[i * 16 + tid];
            }
        }
        if (tid < 16) remw[tid] = removed;
    }
    __syncthreads();

    if (tid < k) {
        const int kp = !((remw[tid >> 6] >> (tid & 63)) & 1ULL);
        d_keep[b][cbase + tid] = (unsigned char)kp;
    }
}

// ---------------------------------------------------------------------------
// K5: per-batch rank assignment (cumsum of keep over sorted order) + output
// ---------------------------------------------------------------------------
__global__ void k_out(float* __restrict__ out) {
    __shared__ unsigned int spos[KCAND];
    __shared__ unsigned char skp[KCAND];
    const int b = blockIdx.x;
    float* ob = out + (size_t)b * POST_NMS * 5;
    for (int i = threadIdx.x; i < POST_NMS * 5; i += blockDim.x) ob[i] = 0.0f;
    for (int i = threadIdx.x; i < KCAND; i += blockDim.x) {
        const unsigned int p = d_sorted_pos[b][i];
        spos[i] = p;
        skp[i] = d_keep[b][p];
    }
    __syncthreads();

    if (threadIdx.x < 32) {
        const int lane = threadIdx.x;
        int rank = 0;
        for (int base = 0; base < KCAND; base += 32) {
            const int i = base + lane;
            const int kpv = (i < KCAND) ? skp[i] : 0;
            const unsigned int mask = __ballot_sync(0xffffffffu, kpv);
            const int myrank = rank + __popc(mask & ((1u << lane) - 1u));
            if (kpv && myrank < POST_NMS) {
                const int pos = (int)spos[i];
                const float4 bx = *(const float4*)&d_cand_box[b][pos][0];
                float* rrow = ob + (size_t)myrank * 5;
                rrow[0] = bx.x; rrow[1] = bx.y; rrow[2] = bx.z; rrow[3] = bx.w;
                rrow[4] = d_cand_sig[b][pos];
            }
            rank += __popc(mask);
            if (rank >= POST_NMS) break;
        }
    }
}

// ---------------------------------------------------------------------------
extern "C" void kernel_launch(void* const* d_in, const int* in_sizes, int n_in,
                              void* d_out, int out_size) {
    const float* obj = (const float*)d_in[0];
    const float* deltas = (const float*)d_in[1];
    const float* anchors = (const float*)d_in[2];
    float* out = (float*)d_out;

    k_topk<<<B * 5, 1024>>>(obj);

    const int total = B * KCAND;
    k_decode<<<(total + 255) / 256, 256>>>(obj, deltas, anchors);

    cudaFuncSetAttribute(k_sort, cudaFuncAttributeMaxDynamicSharedMemorySize,
                         SORT_N * sizeof(unsigned long long));
    k_sort<<<B, 1024, SORT_N * sizeof(unsigned long long)>>>();

    cudaFuncSetAttribute(k_nms, cudaFuncAttributeMaxDynamicSharedMemorySize, NMS_SMEM);
    k_nms<<<B * 5, 1024, NMS_SMEM>>>();

    k_out<<<B, 1024>>>(out);
}

// round 7
// speedup vs baseline: 1.6714x; 1.1383x over previous
#include <cuda_runtime.h>
#include <cuda_bf16.h>
#include <math.h>

#define B 4
#define A_TOTAL 159882
#define KCAND 4507
#define POST_NMS 1000
#define SORT_N 8192
#define NCH 7

__constant__ int c_lvl_n[5]   = {120000, 30000, 7500, 1875, 507};
__constant__ int c_lvl_off[5] = {0, 120000, 150000, 157500, 159375};
__constant__ int c_lvl_k[5]   = {1000, 1000, 1000, 1000, 507};

// static scratch (no allocation allowed)
__device__ unsigned long long d_topk_key[B * 5][1024];
__device__ float              d_cand_box[B][KCAND][4];
__device__ float              d_cand_sig[B][KCAND];
__device__ unsigned char      d_cand_valid[B][KCAND];
__device__ unsigned long long d_sortkey[B][KCAND];
__device__ unsigned int       d_sorted_pos[B][KCAND];
__device__ unsigned char      d_keep[B][KCAND];
__device__ unsigned long long d_mat[B * 5][16000];   // suppression bitmatrix

// monotone float -> u32 (ascending), then inverted for descending sort keys
__device__ __forceinline__ unsigned int fkey_desc(float f) {
    unsigned int b = __float_as_uint(f);
    unsigned int o = (b & 0x80000000u) ? ~b : (b | 0x80000000u);
    return ~o;
}

// ---------------------------------------------------------------------------
// K1: per-(batch,level) exact top-k.
//   2048-bin histogram (warp-aggregated atomics) -> threshold bin,
//   compact (lows + bin-ties) -> one 4096 bitonic sort -> first k keys are
//   exactly top-k (value desc, idx asc). 2 full passes over level data.
// ---------------------------------------------------------------------------
__global__ void k_topk(const float* __restrict__ obj) {
    const int blk = blockIdx.x;
    const int b = blk / 5, l = blk % 5;
    const int n = c_lvl_n[l], off = c_lvl_off[l], k = c_lvl_k[l];
    const float* row = obj + (size_t)b * A_TOTAL + off;

    __shared__ unsigned int hist[2048];
    __shared__ unsigned int wsum[32];
    __shared__ int sh_bin;
    __shared__ int cntL, cntT;
    __shared__ unsigned long long skey[4096];

    for (int i = threadIdx.x; i < 2048; i += 1024) hist[i] = 0;
    for (int i = threadIdx.x; i < 4096; i += 1024) skey[i] = ~0ULL;
    if (threadIdx.x == 0) { cntL = 0; cntT = 0; sh_bin = 1 << 29; }
    __syncthreads();

    if (k < n) {
        const int lane = threadIdx.x & 31;
        for (int base = 0; base < n; base += 1024) {
            const int i = base + threadIdx.x;
            const unsigned int active = __ballot_sync(0xffffffffu, i < n);
            if (i < n) {
                const unsigned int bin = fkey_desc(row[i]) >> 21;
                const unsigned int mm = __match_any_sync(active, bin);
                if (lane == (__ffs(mm) - 1))
                    atomicAdd(&hist[bin], (unsigned int)__popc(mm));
            }
        }
        __syncthreads();
        const int wid = threadIdx.x >> 5, lane2 = threadIdx.x & 31;
        {
            unsigned int s = hist[wid * 64 + lane2] + hist[wid * 64 + 32 + lane2];
#pragma unroll
            for (int d = 16; d > 0; d >>= 1) s += __shfl_down_sync(0xffffffffu, s, d);
            if (lane2 == 0) wsum[wid] = s;
        }
        __syncthreads();
        if (threadIdx.x == 0) {
            unsigned int cum = 0; int g = 0;
            while (g < 32 && cum + wsum[g] < (unsigned int)k) { cum += wsum[g]; g++; }
            int bin = g * 64;
            while (cum + hist[bin] < (unsigned int)k) { cum += hist[bin]; bin++; }
            sh_bin = bin;
        }
        __syncthreads();
    }
    const int bin = sh_bin;

    for (int i = threadIdx.x; i < n; i += 1024) {
        const unsigned long long key =
            ((unsigned long long)fkey_desc(row[i]) << 32) | (unsigned int)i;
        const int hb = (int)(key >> 53);
        if (hb < bin) {
            int p = atomicAdd(&cntL, 1);
            if (p < 2048) skey[p] = key;
        } else if (hb == bin) {
            int p = atomicAdd(&cntT, 1);
            if (p < 2048) skey[2048 + p] = key;
        }
    }
    __syncthreads();

    // bitonic sort 4096 ascending (=> logit desc, idx asc)
    for (int size = 2; size <= 4096; size <<= 1) {
        for (int stride = size >> 1; stride > 0; stride >>= 1) {
            for (int t = threadIdx.x; t < 2048; t += 1024) {
                const int i = ((t / stride) * (stride << 1)) + (t & (stride - 1));
                const int j = i + stride;
                const bool asc = ((i & size) == 0);
                unsigned long long a = skey[i], bb = skey[j];
                if (asc ? (a > bb) : (a < bb)) { skey[i] = bb; skey[j] = a; }
            }
            __syncthreads();
        }
    }
    if (threadIdx.x < k) d_topk_key[blk][threadIdx.x] = skey[threadIdx.x];
}

// ---------------------------------------------------------------------------
// K2: decode + sigmoid + clip + valid + global-sort key, per selected candidate
// ---------------------------------------------------------------------------
__global__ void k_decode(const float* __restrict__ obj,
                         const float* __restrict__ deltas,
                         const float* __restrict__ anchors) {
    const int g = blockIdx.x * blockDim.x + threadIdx.x;
    if (g >= B * KCAND) return;
    const int b = g / KCAND;
    const int pos = g - b * KCAND;
    const int l = pos / 1000;                 // cand layout: 1000,1000,1000,1000,507
    const int r = pos - l * 1000;

    const unsigned long long key = d_topk_key[b * 5 + l][r];
    const unsigned int idx = (unsigned int)key;
    const int a = c_lvl_off[l] + (int)idx;

    const float logit = obj[(size_t)b * A_TOTAL + a];

    const float4 an = *(const float4*)(anchors + (size_t)a * 4);
    const float4 dl = *(const float4*)(deltas + ((size_t)b * A_TOTAL + a) * 4);

    const float BBOX_CLIP = (float)4.135166556742356;

    const float wa = __fsub_rn(an.z, an.x);
    const float ha = __fsub_rn(an.w, an.y);
    const float cxa = __fadd_rn(an.x, __fmul_rn(0.5f, wa));
    const float cya = __fadd_rn(an.y, __fmul_rn(0.5f, ha));

    const float dx = dl.x, dy = dl.y;
    const float dw = fminf(dl.z, BBOX_CLIP);
    const float dh = fminf(dl.w, BBOX_CLIP);

    const float cx = __fadd_rn(__fmul_rn(dx, wa), cxa);
    const float cy = __fadd_rn(__fmul_rn(dy, ha), cya);
    const float w = __fmul_rn(expf(dw), wa);
    const float h = __fmul_rn(expf(dh), ha);

    const float hw = __fmul_rn(0.5f, w);
    const float hh = __fmul_rn(0.5f, h);
    float x1 = __fsub_rn(cx, hw);
    float y1 = __fsub_rn(cy, hh);
    float x2 = __fadd_rn(cx, hw);
    float y2 = __fadd_rn(cy, hh);

    x1 = fminf(fmaxf(x1, 0.0f), 800.0f);
    y1 = fminf(fmaxf(y1, 0.0f), 800.0f);
    x2 = fminf(fmaxf(x2, 0.0f), 800.0f);
    y2 = fminf(fmaxf(y2, 0.0f), 800.0f);

    // sigmoid = 1 / (1 + exp(-x))   (XLA LogisticExpander)
    const float sig = __fdiv_rn(1.0f, __fadd_rn(1.0f, expf(-logit)));

    const bool valid = (__fsub_rn(x2, x1) >= 0.001f) &&
                       (__fsub_rn(y2, y1) >= 0.001f) &&
                       (sig >= 0.0f);

    d_cand_box[b][pos][0] = x1;
    d_cand_box[b][pos][1] = y1;
    d_cand_box[b][pos][2] = x2;
    d_cand_box[b][pos][3] = y2;
    d_cand_sig[b][pos] = sig;
    d_cand_valid[b][pos] = valid ? 1 : 0;

    const float sigp = valid ? sig : __int_as_float(0xff800000); // -inf
    d_sortkey[b][pos] = ((unsigned long long)fkey_desc(sigp) << 32) | (unsigned int)pos;
}

// ---------------------------------------------------------------------------
// K3: per-batch stable sort (score desc, candpos asc) via bitonic on 8192 keys
// ---------------------------------------------------------------------------
extern __shared__ unsigned long long s_sort[];
__global__ void k_sort() {
    const int b = blockIdx.x;
    for (int i = threadIdx.x; i < SORT_N; i += blockDim.x)
        s_sort[i] = (i < KCAND) ? d_sortkey[b][i] : ~0ULL;
    __syncthreads();
    for (int size = 2; size <= SORT_N; size <<= 1) {
        for (int stride = size >> 1; stride > 0; stride >>= 1) {
            for (int t = threadIdx.x; t < SORT_N / 2; t += blockDim.x) {
                const int i = ((t / stride) * (stride << 1)) + (t & (stride - 1));
                const int j = i + stride;
                const bool asc = ((i & size) == 0);
                unsigned long long a = s_sort[i], bb = s_sort[j];
                if (asc ? (a > bb) : (a < bb)) { s_sort[i] = bb; s_sort[j] = a; }
            }
            __syncthreads();
        }
    }
    for (int i = threadIdx.x; i < KCAND; i += blockDim.x)
        d_sorted_pos[b][i] = (unsigned int)s_sort[i];
}

// ---------------------------------------------------------------------------
// iou(i,j) > 0.7 — identical arithmetic to the reference
// ---------------------------------------------------------------------------
__device__ __forceinline__ bool iou_gt(const float4 bi, const float ai,
                                       const float4 bj, const float aj) {
    const float xx1 = fmaxf(bi.x, bj.x);
    const float yy1 = fmaxf(bi.y, bj.y);
    const float xx2 = fminf(bi.z, bj.z);
    const float yy2 = fminf(bi.w, bj.w);
    const float ww = fmaxf(__fsub_rn(xx2, xx1), 0.0f);
    const float hh = fmaxf(__fsub_rn(yy2, yy1), 0.0f);
    const float inter = __fmul_rn(ww, hh);
    const float uni = __fsub_rn(__fadd_rn(ai, aj), inter);
    return __fdiv_rn(inter, uni) > 0.7f;
}

// ---------------------------------------------------------------------------
// K4a: suppression bitmatrix build, 140 blocks (7 row-chunks per (b,l)).
//   Warp-per-(row,word): 32 lanes compute 64 IoUs -> ballot into u64.
// ---------------------------------------------------------------------------
#define BUILD_SMEM (16000 + 4000)
__global__ void k_nms_build() {
    extern __shared__ unsigned char dynb[];
    float4* sbox = (float4*)dynb;            // [1000]
    float*  sar  = (float*)(dynb + 16000);   // [1000]

    const int blk = blockIdx.x;
    const int group = blk / NCH, chunk = blk % NCH;
    const int b = group / 5, l = group % 5;
    const int k = c_lvl_k[l];
    const int cbase = l * 1000;
    const float loff = (float)l * 1000.0f;

    for (int r = threadIdx.x; r < k; r += 1024) {
        const int pos = cbase + r;
        const float ox1 = __fadd_rn(d_cand_box[b][pos][0], loff);
        const float oy1 = __fadd_rn(d_cand_box[b][pos][1], loff);
        const float ox2 = __fadd_rn(d_cand_box[b][pos][2], loff);
        const float oy2 = __fadd_rn(d_cand_box[b][pos][3], loff);
        sbox[r] = make_float4(ox1, oy1, ox2, oy2);
        sar[r] = __fmul_rn(__fsub_rn(ox2, ox1), __fsub_rn(oy2, oy1));
    }
    __syncthreads();

    const int wid = threadIdx.x >> 5, lane = threadIdx.x & 31;
    const int nrows = (k - chunk + NCH - 1) / NCH;
    const int ntasks = nrows * 16;
    for (int t = wid; t < ntasks; t += 32) {
        const int r = chunk + (t >> 4) * NCH;   // warp-uniform
        const int w = t & 15;
        unsigned long long word = 0ULL;
        if ((w << 6) + 63 > r) {                // word has bits above diagonal
            const float4 bi = sbox[r];
            const float ai = sar[r];
            const int j1 = (w << 6) + lane;
            const int j2 = j1 + 32;
            bool v1 = false, v2 = false;
            if (j1 > r && j1 < k) v1 = iou_gt(bi, ai, sbox[j1], sar[j1]);
            if (j2 > r && j2 < k) v2 = iou_gt(bi, ai, sbox[j2], sar[j2]);
            const unsigned int lo = __ballot_sync(0xffffffffu, v1);
            const unsigned int hi = __ballot_sync(0xffffffffu, v2);
            word = (unsigned long long)lo | ((unsigned long long)hi << 32);
        }
        if (lane == 0) d_mat[group][r * 16 + w] = word;
    }
}

// ---------------------------------------------------------------------------
// K4b: greedy scan, 20 blocks. Stage matrix to smem, 1-shfl per kept box.
// dyn smem: smat u64[16000] | ball u32[32] | remw u64[16]
// ---------------------------------------------------------------------------
#define SCAN_SMEM (128000 + 128 + 128)
__global__ void k_nms_scan() {
    extern __shared__ unsigned char dyns[];
    unsigned long long* smat = (unsigned long long*)dyns;               // [16000]
    unsigned int* ball = (unsigned int*)(dyns + 128000);                // [32]
    unsigned long long* remw = (unsigned long long*)(dyns + 128128);    // [16]

    const int group = blockIdx.x;
    const int b = group / 5, l = group % 5;
    const int k = c_lvl_k[l];
    const int cbase = l * 1000;
    const int tid = threadIdx.x;

    const int nwords = k * 16;
    for (int i = tid; i < nwords; i += 1024) smat[i] = d_mat[group][i];

    int valid_flag = (tid < k) ? d_cand_valid[b][cbase + tid] : 0;
    const unsigned int bal = __ballot_sync(0xffffffffu, valid_flag);
    if ((tid & 31) == 0) ball[tid >> 5] = bal;
    __syncthreads();

    if (tid < 32) {
        const int lane = tid;
        unsigned long long removed = ~0ULL, done = 0ULL;
        if (lane < 16) {
            const unsigned long long lo = ball[lane * 2];
            const unsigned long long hi = ball[lane * 2 + 1];
            removed = ~(lo | (hi << 32));
        }
        const int nw = (k + 63) >> 6;
        for (int w = 0; w < nw; w++) {
            while (true) {
                const unsigned long long live = ~removed & ~done;
                int bit = live ? (__ffsll((long long)live) - 1) : 64;
                bit = __shfl_sync(0xffffffffu, bit, w);
                if (bit == 64) break;
                const int i = (w << 6) + bit;
                if (lane == w) done |= 1ULL << bit;
                if (lane < 16) removed |= smat[i * 16 + lane];
            }
        }
        if (lane < 16) remw[lane] = removed;
    }
    __syncthreads();

    if (tid < k) {
        const int kp = !((remw[tid >> 6] >> (tid & 63)) & 1ULL);
        d_keep[b][cbase + tid] = (unsigned char)kp;
    }
}

// ---------------------------------------------------------------------------
// K5: per-batch rank assignment (cumsum of keep over sorted order) + output
// ---------------------------------------------------------------------------
__global__ void k_out(float* __restrict__ out) {
    __shared__ unsigned int spos[KCAND];
    __shared__ unsigned char skp[KCAND];
    const int b = blockIdx.x;
    float* ob = out + (size_t)b * POST_NMS * 5;
    for (int i = threadIdx.x; i < POST_NMS * 5; i += blockDim.x) ob[i] = 0.0f;
    for (int i = threadIdx.x; i < KCAND; i += blockDim.x) {
        const unsigned int p = d_sorted_pos[b][i];
        spos[i] = p;
        skp[i] = d_keep[b][p];
    }
    __syncthreads();

    if (threadIdx.x < 32) {
        const int lane = threadIdx.x;
        int rank = 0;
        for (int base = 0; base < KCAND; base += 32) {
            const int i = base + lane;
            const int kpv = (i < KCAND) ? skp[i] : 0;
            const unsigned int mask = __ballot_sync(0xffffffffu, kpv);
            const int myrank = rank + __popc(mask & ((1u << lane) - 1u));
            if (kpv && myrank < POST_NMS) {
                const int pos = (int)spos[i];
                const float4 bx = *(const float4*)&d_cand_box[b][pos][0];
                float* rrow = ob + (size_t)myrank * 5;
                rrow[0] = bx.x; rrow[1] = bx.y; rrow[2] = bx.z; rrow[3] = bx.w;
                rrow[4] = d_cand_sig[b][pos];
            }
            rank += __popc(mask);
            if (rank >= POST_NMS) break;
        }
    }
}

// ---------------------------------------------------------------------------
extern "C" void kernel_launch(void* const* d_in, const int* in_sizes, int n_in,
                              void* d_out, int out_size) {
    const float* obj = (const float*)d_in[0];
    const float* deltas = (const float*)d_in[1];
    const float* anchors = (const float*)d_in[2];
    float* out = (float*)d_out;

    k_topk<<<B * 5, 1024>>>(obj);

    const int total = B * KCAND;
    k_decode<<<(total + 255) / 256, 256>>>(obj, deltas, anchors);

    cudaFuncSetAttribute(k_sort, cudaFuncAttributeMaxDynamicSharedMemorySize,
                         SORT_N * sizeof(unsigned long long));
    k_sort<<<B, 1024, SORT_N * sizeof(unsigned long long)>>>();

    k_nms_build<<<B * 5 * NCH, 1024, BUILD_SMEM>>>();

    cudaFuncSetAttribute(k_nms_scan, cudaFuncAttributeMaxDynamicSharedMemorySize, SCAN_SMEM);
    k_nms_scan<<<B * 5, 1024, SCAN_SMEM>>>();

    k_out<<<B, 1024>>>(out);
}

// round 11
// speedup vs baseline: 2.3452x; 1.4031x over previous
#include <cuda_runtime.h>
#include <cuda_bf16.h>
#include <math.h>

#define B 4
#define A_TOTAL 159882
#define KCAND 4507
#define POST_NMS 1000
#define SORT_N 8192
#define NCH 14

__constant__ int c_lvl_n[5]   = {120000, 30000, 7500, 1875, 507};
__constant__ int c_lvl_off[5] = {0, 120000, 150000, 157500, 159375};
__constant__ int c_lvl_k[5]   = {1000, 1000, 1000, 1000, 507};

// static scratch (no allocation allowed)
__device__ unsigned long long d_topk_key[B * 5][1024];
__device__ float              d_cand_box[B][KCAND][4];
__device__ float              d_cand_sig[B][KCAND];
__device__ unsigned char      d_cand_valid[B][KCAND];
__device__ unsigned long long d_sortkey[B][KCAND];
__device__ unsigned int       d_sorted_pos[B][KCAND];
__device__ unsigned char      d_keep[B][KCAND];
__device__ unsigned long long d_mat[B * 5][16000];   // suppression bitmatrix

// monotone float -> u32 (ascending), then inverted for descending sort keys
__device__ __forceinline__ unsigned int fkey_desc(float f) {
    unsigned int b = __float_as_uint(f);
    unsigned int o = (b & 0x80000000u) ? ~b : (b | 0x80000000u);
    return ~o;
}

// ---------------------------------------------------------------------------
// K1: per-(batch,level) exact top-k.
// ---------------------------------------------------------------------------
__global__ void k_topk(const float* __restrict__ obj) {
    const int blk = blockIdx.x;
    const int b = blk / 5, l = blk % 5;
    const int n = c_lvl_n[l], off = c_lvl_off[l], k = c_lvl_k[l];
    const float* row = obj + (size_t)b * A_TOTAL + off;

    __shared__ unsigned int hist[2048];
    __shared__ unsigned int wsum[32];
    __shared__ int sh_bin;
    __shared__ int cntL, cntT;
    __shared__ unsigned long long skey[4096];

    for (int i = threadIdx.x; i < 2048; i += 1024) hist[i] = 0;
    for (int i = threadIdx.x; i < 4096; i += 1024) skey[i] = ~0ULL;
    if (threadIdx.x == 0) { cntL = 0; cntT = 0; sh_bin = 1 << 29; }
    __syncthreads();

    if (k < n) {
        const int lane = threadIdx.x & 31;
        for (int base = 0; base < n; base += 1024) {
            const int i = base + threadIdx.x;
            const unsigned int active = __ballot_sync(0xffffffffu, i < n);
            if (i < n) {
                const unsigned int bin = fkey_desc(row[i]) >> 21;
                const unsigned int mm = __match_any_sync(active, bin);
                if (lane == (__ffs(mm) - 1))
                    atomicAdd(&hist[bin], (unsigned int)__popc(mm));
            }
        }
        __syncthreads();
        const int wid = threadIdx.x >> 5, lane2 = threadIdx.x & 31;
        {
            unsigned int s = hist[wid * 64 + lane2] + hist[wid * 64 + 32 + lane2];
#pragma unroll
            for (int d = 16; d > 0; d >>= 1) s += __shfl_down_sync(0xffffffffu, s, d);
            if (lane2 == 0) wsum[wid] = s;
        }
        __syncthreads();
        if (threadIdx.x == 0) {
            unsigned int cum = 0; int g = 0;
            while (g < 32 && cum + wsum[g] < (unsigned int)k) { cum += wsum[g]; g++; }
            int bin = g * 64;
            while (cum + hist[bin] < (unsigned int)k) { cum += hist[bin]; bin++; }
            sh_bin = bin;
        }
        __syncthreads();
    }
    const int bin = sh_bin;

    for (int i = threadIdx.x; i < n; i += 1024) {
        const unsigned long long key =
            ((unsigned long long)fkey_desc(row[i]) << 32) | (unsigned int)i;
        const int hb = (int)(key >> 53);
        if (hb < bin) {
            int p = atomicAdd(&cntL, 1);
            if (p < 2048) skey[p] = key;
        } else if (hb == bin) {
            int p = atomicAdd(&cntT, 1);
            if (p < 2048) skey[2048 + p] = key;
        }
    }
    __syncthreads();

    // bitonic sort 4096 ascending (=> logit desc, idx asc)
    for (int size = 2; size <= 4096; size <<= 1) {
        for (int stride = size >> 1; stride > 0; stride >>= 1) {
            for (int t = threadIdx.x; t < 2048; t += 1024) {
                const int i = ((t / stride) * (stride << 1)) + (t & (stride - 1));
                const int j = i + stride;
                const bool asc = ((i & size) == 0);
                unsigned long long a = skey[i], bb = skey[j];
                if (asc ? (a > bb) : (a < bb)) { skey[i] = bb; skey[j] = a; }
            }
            __syncthreads();
        }
    }
    if (threadIdx.x < k) d_topk_key[blk][threadIdx.x] = skey[threadIdx.x];
}

// ---------------------------------------------------------------------------
// K2: decode + sigmoid + clip + valid + global-sort key
// ---------------------------------------------------------------------------
__global__ void k_decode(const float* __restrict__ obj,
                         const float* __restrict__ deltas,
                         const float* __restrict__ anchors) {
    const int g = blockIdx.x * blockDim.x + threadIdx.x;
    if (g >= B * KCAND) return;
    const int b = g / KCAND;
    const int pos = g - b * KCAND;
    const int l = pos / 1000;
    const int r = pos - l * 1000;

    const unsigned long long key = d_topk_key[b * 5 + l][r];
    const unsigned int idx = (unsigned int)key;
    const int a = c_lvl_off[l] + (int)idx;

    const float logit = obj[(size_t)b * A_TOTAL + a];

    const float4 an = *(const float4*)(anchors + (size_t)a * 4);
    const float4 dl = *(const float4*)(deltas + ((size_t)b * A_TOTAL + a) * 4);

    const float BBOX_CLIP = (float)4.135166556742356;

    const float wa = __fsub_rn(an.z, an.x);
    const float ha = __fsub_rn(an.w, an.y);
    const float cxa = __fadd_rn(an.x, __fmul_rn(0.5f, wa));
    const float cya = __fadd_rn(an.y, __fmul_rn(0.5f, ha));

    const float dx = dl.x, dy = dl.y;
    const float dw = fminf(dl.z, BBOX_CLIP);
    const float dh = fminf(dl.w, BBOX_CLIP);

    const float cx = __fadd_rn(__fmul_rn(dx, wa), cxa);
    const float cy = __fadd_rn(__fmul_rn(dy, ha), cya);
    const float w = __fmul_rn(expf(dw), wa);
    const float h = __fmul_rn(expf(dh), ha);

    const float hw = __fmul_rn(0.5f, w);
    const float hh = __fmul_rn(0.5f, h);
    float x1 = __fsub_rn(cx, hw);
    float y1 = __fsub_rn(cy, hh);
    float x2 = __fadd_rn(cx, hw);
    float y2 = __fadd_rn(cy, hh);

    x1 = fminf(fmaxf(x1, 0.0f), 800.0f);
    y1 = fminf(fmaxf(y1, 0.0f), 800.0f);
    x2 = fminf(fmaxf(x2, 0.0f), 800.0f);
    y2 = fminf(fmaxf(y2, 0.0f), 800.0f);

    const float sig = __fdiv_rn(1.0f, __fadd_rn(1.0f, expf(-logit)));

    const bool valid = (__fsub_rn(x2, x1) >= 0.001f) &&
                       (__fsub_rn(y2, y1) >= 0.001f) &&
                       (sig >= 0.0f);

    d_cand_box[b][pos][0] = x1;
    d_cand_box[b][pos][1] = y1;
    d_cand_box[b][pos][2] = x2;
    d_cand_box[b][pos][3] = y2;
    d_cand_sig[b][pos] = sig;
    d_cand_valid[b][pos] = valid ? 1 : 0;

    const float sigp = valid ? sig : __int_as_float(0xff800000); // -inf
    d_sortkey[b][pos] = ((unsigned long long)fkey_desc(sigp) << 32) | (unsigned int)pos;
}

// ---------------------------------------------------------------------------
// K3: per-batch stable sort via bitonic on 8192 keys
// ---------------------------------------------------------------------------
extern __shared__ unsigned long long s_sort[];
__global__ void k_sort() {
    const int b = blockIdx.x;
    for (int i = threadIdx.x; i < SORT_N; i += blockDim.x)
        s_sort[i] = (i < KCAND) ? d_sortkey[b][i] : ~0ULL;
    __syncthreads();
    for (int size = 2; size <= SORT_N; size <<= 1) {
        for (int stride = size >> 1; stride > 0; stride >>= 1) {
            for (int t = threadIdx.x; t < SORT_N / 2; t += blockDim.x) {
                const int i = ((t / stride) * (stride << 1)) + (t & (stride - 1));
                const int j = i + stride;
                const bool asc = ((i & size) == 0);
                unsigned long long a = s_sort[i], bb = s_sort[j];
                if (asc ? (a > bb) : (a < bb)) { s_sort[i] = bb; s_sort[j] = a; }
            }
            __syncthreads();
        }
    }
    for (int i = threadIdx.x; i < KCAND; i += blockDim.x)
        d_sorted_pos[b][i] = (unsigned int)s_sort[i];
}

// ---------------------------------------------------------------------------
// iou(i,j) > 0.7 — identical arithmetic to the reference
// ---------------------------------------------------------------------------
__device__ __forceinline__ bool iou_gt(const float4 bi, const float ai,
                                       const float4 bj, const float aj) {
    const float xx1 = fmaxf(bi.x, bj.x);
    const float yy1 = fmaxf(bi.y, bj.y);
    const float xx2 = fminf(bi.z, bj.z);
    const float yy2 = fminf(bi.w, bj.w);
    const float ww = fmaxf(__fsub_rn(xx2, xx1), 0.0f);
    const float hh = fmaxf(__fsub_rn(yy2, yy1), 0.0f);
    const float inter = __fmul_rn(ww, hh);
    const float uni = __fsub_rn(__fadd_rn(ai, aj), inter);
    return __fdiv_rn(inter, uni) > 0.7f;
}

// ---------------------------------------------------------------------------
// K4a: suppression bitmatrix build, upper-triangle words only.
//   280 blocks (14 row-chunks per (b,l)), 512 threads, warp-per-(row,word).
// ---------------------------------------------------------------------------
#define BUILD_SMEM (16000 + 4000)
__global__ void k_nms_build() {
    extern __shared__ unsigned char dynb[];
    float4* sbox = (float4*)dynb;            // [1000]
    float*  sar  = (float*)(dynb + 16000);   // [1000]

    const int blk = blockIdx.x;
    const int group = blk / NCH, chunk = blk % NCH;
    const int b = group / 5, l = group % 5;
    const int k = c_lvl_k[l];
    const int cbase = l * 1000;
    const float loff = (float)l * 1000.0f;

    for (int r = threadIdx.x; r < k; r += blockDim.x) {
        const int pos = cbase + r;
        const float ox1 = __fadd_rn(d_cand_box[b][pos][0], loff);
        const float oy1 = __fadd_rn(d_cand_box[b][pos][1], loff);
        const float ox2 = __fadd_rn(d_cand_box[b][pos][2], loff);
        const float oy2 = __fadd_rn(d_cand_box[b][pos][3], loff);
        sbox[r] = make_float4(ox1, oy1, ox2, oy2);
        sar[r] = __fmul_rn(__fsub_rn(ox2, ox1), __fsub_rn(oy2, oy1));
    }
    __syncthreads();

    const int wid = threadIdx.x >> 5, lane = threadIdx.x & 31;
    const int nwarps = blockDim.x >> 5;
    const int nrows = (k - chunk + NCH - 1) / NCH;
    const int ntasks = nrows * 16;
    for (int t = wid; t < ntasks; t += nwarps) {
        const int r = chunk + (t >> 4) * NCH;   // warp-uniform
        const int w = t & 15;
        if (w < (r >> 6)) continue;             // sub-diagonal: never read
        unsigned long long word = 0ULL;
        if ((w << 6) + 63 > r) {
            const float4 bi = sbox[r];
            const float ai = sar[r];
            const int j1 = (w << 6) + lane;
            const int j2 = j1 + 32;
            bool v1 = false, v2 = false;
            if (j1 > r && j1 < k) v1 = iou_gt(bi, ai, sbox[j1], sar[j1]);
            if (j2 > r && j2 < k) v2 = iou_gt(bi, ai, sbox[j2], sar[j2]);
            const unsigned int lo = __ballot_sync(0xffffffffu, v1);
            const unsigned int hi = __ballot_sync(0xffffffffu, v2);
            word = (unsigned long long)lo | ((unsigned long long)hi << 32);
        }
        if (lane == 0) d_mat[group][r * 16 + w] = word;
    }
}

// ---------------------------------------------------------------------------
// K4b: greedy scan exploiting sparsity. 20 blocks.
//   Per 64-word: parallel diag prefetch + nz ballot; serial loop only over
//   live&nz bits; cross-OR only over kept rows that have any bits (rowNZ).
// dyn smem: smat u64[16000] | ball u32[32] | remw u64[16] | rowNZ u64[16]
// ---------------------------------------------------------------------------
#define SCAN_SMEM (128000 + 128 + 128 + 128)
__global__ void k_nms_scan() {
    extern __shared__ unsigned char dyns[];
    unsigned long long* smat = (unsigned long long*)dyns;               // [16000]
    unsigned int* ball = (unsigned int*)(dyns + 128000);                // [32]
    unsigned long long* remw = (unsigned long long*)(dyns + 128128);    // [16]
    unsigned long long* rowNZ = (unsigned long long*)(dyns + 128256);   // [16]

    const int group = blockIdx.x;
    const int b = group / 5, l = group % 5;
    const int k = c_lvl_k[l];
    const int cbase = l * 1000;
    const int tid = threadIdx.x;

    if (tid < 16) rowNZ[tid] = 0ULL;
    __syncthreads();

    const int nwords = k * 16;
    for (int i = tid; i < nwords; i += 1024) {
        const unsigned long long v = d_mat[group][i];
        smat[i] = v;
        const int r = i >> 4, w = i & 15;
        if (v != 0ULL && w >= (r >> 6))
            atomicOr(&rowNZ[r >> 6], 1ULL << (r & 63));
    }

    int valid_flag = (tid < k) ? d_cand_valid[b][cbase + tid] : 0;
    const unsigned int bal = __ballot_sync(0xffffffffu, valid_flag);
    if ((tid & 31) == 0) ball[tid >> 5] = bal;
    __syncthreads();

    if (tid < 32) {
        const int lane = tid;
        unsigned long long removed = ~0ULL;
        if (lane < 16) {
            const unsigned long long lo = ball[lane * 2];
            const unsigned long long hi = ball[lane * 2 + 1];
            removed = ~(lo | (hi << 32));
        }
        const int nw = (k + 63) >> 6;
        for (int w = 0; w < nw; w++) {
            // initial removed state of word w (broadcast from owning lane)
            const unsigned long long rw0 = __shfl_sync(0xffffffffu, removed, w);
            unsigned long long live0 = ~rw0;
            if (!live0) continue;

            // parallel diag prefetch: lane holds rows (w<<6)+lane, +lane+32
            const int r0 = (w << 6) + lane;
            const int r1 = r0 + 32;
            const unsigned long long m0 = (r0 < k) ? smat[(r0 << 4) + w] : 0ULL;
            const unsigned long long m1 = (r1 < k) ? smat[(r1 << 4) + w] : 0ULL;
            const unsigned int nzlo = __ballot_sync(0xffffffffu, m0 != 0ULL);
            const unsigned int nzhi = __ballot_sync(0xffffffffu, m1 != 0ULL);
            const unsigned long long nz =
                (unsigned long long)nzlo | ((unsigned long long)nzhi << 32);

            // intra-word greedy resolution, only rows that can suppress
            unsigned long long rm = rw0;
            unsigned long long ser = live0 & nz;
            while (ser) {
                const int bit = __ffsll((long long)ser) - 1;
                ser &= ser - 1ULL;
                if (!((rm >> bit) & 1ULL)) {
                    const unsigned long long mb = __shfl_sync(
                        0xffffffffu, (bit < 32) ? m0 : m1, bit & 31);
                    rm |= mb;
                    ser &= ~rm;
                }
            }
            const unsigned long long kept = live0 & ~rm;
            if (lane == w) removed = rm;

            // cross-word OR: only kept rows with any suppression bits
            unsigned long long it = kept & rowNZ[w];
            while (it) {
                const int i = __ffsll((long long)it) - 1;
                it &= it - 1ULL;
                if (lane > w && lane < 16)
                    removed |= smat[(((w << 6) + i) << 4) + lane];
            }
        }
        if (lane < 16) remw[lane] = removed;
    }
    __syncthreads();

    if (tid < k) {
        const int kp = !((remw[tid >> 6] >> (tid & 63)) & 1ULL);
        d_keep[b][cbase + tid] = (unsigned char)kp;
    }
}

// ---------------------------------------------------------------------------
// K5: per-batch rank assignment + output
// ---------------------------------------------------------------------------
__global__ void k_out(float* __restrict__ out) {
    __shared__ unsigned int spos[KCAND];
    __shared__ unsigned char skp[KCAND];
    const int b = blockIdx.x;
    float* ob = out + (size_t)b * POST_NMS * 5;
    for (int i = threadIdx.x; i < POST_NMS * 5; i += blockDim.x) ob[i] = 0.0f;
    for (int i = threadIdx.x; i < KCAND; i += blockDim.x) {
        const unsigned int p = d_sorted_pos[b][i];
        spos[i] = p;
        skp[i] = d_keep[b][p];
    }
    __syncthreads();

    if (threadIdx.x < 32) {
        const int lane = threadIdx.x;
        int rank = 0;
        for (int base = 0; base < KCAND; base += 32) {
            const int i = base + lane;
            const int kpv = (i < KCAND) ? skp[i] : 0;
            const unsigned int mask = __ballot_sync(0xffffffffu, kpv);
            const int myrank = rank + __popc(mask & ((1u << lane) - 1u));
            if (kpv && myrank < POST_NMS) {
                const int pos = (int)spos[i];
                const float4 bx = *(const float4*)&d_cand_box[b][pos][0];
                float* rrow = ob + (size_t)myrank * 5;
                rrow[0] = bx.x; rrow[1] = bx.y; rrow[2] = bx.z; rrow[3] = bx.w;
                rrow[4] = d_cand_sig[b][pos];
            }
            rank += __popc(mask);
            if (rank >= POST_NMS) break;
        }
    }
}

// ---------------------------------------------------------------------------
extern "C" void kernel_launch(void* const* d_in, const int* in_sizes, int n_in,
                              void* d_out, int out_size) {
    const float* obj = (const float*)d_in[0];
    const float* deltas = (const float*)d_in[1];
    const float* anchors = (const float*)d_in[2];
    float* out = (float*)d_out;

    k_topk<<<B * 5, 1024>>>(obj);

    const int total = B * KCAND;
    k_decode<<<(total + 255) / 256, 256>>>(obj, deltas, anchors);

    cudaFuncSetAttribute(k_sort, cudaFuncAttributeMaxDynamicSharedMemorySize,
                         SORT_N * sizeof(unsigned long long));
    k_sort<<<B, 1024, SORT_N * sizeof(unsigned long long)>>>();

    k_nms_build<<<B * 5 * NCH, 512, BUILD_SMEM>>>();

    cudaFuncSetAttribute(k_nms_scan, cudaFuncAttributeMaxDynamicSharedMemorySize, SCAN_SMEM);
    k_nms_scan<<<B * 5, 1024, SCAN_SMEM>>>();

    k_out<<<B, 1024>>>(out);
}

// round 15
// speedup vs baseline: 3.9031x; 1.6643x over previous
#include <cuda_runtime.h>
#include <cuda_bf16.h>
#include <math.h>

#define B 4
#define A_TOTAL 159882
#define KCAND 4507
#define POST_NMS 1000
#define NCH 14
#define HCH 8

__constant__ int c_lvl_n[5]   = {120000, 30000, 7500, 1875, 507};
__constant__ int c_lvl_off[5] = {0, 120000, 150000, 157500, 159375};
__constant__ int c_lvl_k[5]   = {1000, 1000, 1000, 1000, 507};

// static scratch (no allocation allowed)
__device__ unsigned int       d_hist[B * 5][2048];
__device__ float              d_cand_box[B][KCAND][4];
__device__ float              d_cand_sig[B][KCAND];
__device__ unsigned char      d_cand_valid[B][KCAND];
__device__ unsigned long long d_sortbuf[B][8192];
__device__ unsigned int       d_sorted_pos[B][KCAND];
__device__ unsigned char      d_keep[B][KCAND];
__device__ unsigned long long d_mat[B * 5][16000];   // suppression bitmatrix

// monotone float -> u32 (ascending), then inverted for descending sort keys
__device__ __forceinline__ unsigned int fkey_desc(float f) {
    unsigned int b = __float_as_uint(f);
    unsigned int o = (b & 0x80000000u) ? ~b : (b | 0x80000000u);
    return ~o;
}

// ---------------------------------------------------------------------------
// K0: partial histograms (warp-aggregated global atomics), 160 blocks
// ---------------------------------------------------------------------------
__global__ void k_hist(const float* __restrict__ obj) {
    const int blk = blockIdx.x;
    const int group = blk / HCH, chunk = blk % HCH;
    const int b = group / 5, l = group % 5;
    const int n = c_lvl_n[l], off = c_lvl_off[l], k = c_lvl_k[l];
    if (k >= n) return;
    const float* row = obj + (size_t)b * A_TOTAL + off;
    const int slice = (n + HCH - 1) / HCH;
    const int lo = chunk * slice;
    const int hi = min(n, lo + slice);
    const int lane = threadIdx.x & 31;
    for (int base = lo; base < hi; base += blockDim.x) {
        const int i = base + threadIdx.x;
        const unsigned int active = __ballot_sync(0xffffffffu, i < hi);
        if (i < hi) {
            const unsigned int bin = fkey_desc(row[i]) >> 21;
            const unsigned int mm = __match_any_sync(active, bin);
            if (lane == (__ffs(mm) - 1))
                atomicAdd(&d_hist[group][bin], (unsigned int)__popc(mm));
        }
    }
}

// ---------------------------------------------------------------------------
// K1: per-(batch,level) exact top-k (bin select + compact + bitonic 4096)
//     with FUSED decode/sigmoid/clip/valid/sort-key epilogue.
// ---------------------------------------------------------------------------
__global__ void k_topk(const float* __restrict__ obj,
                       const float* __restrict__ deltas,
                       const float* __restrict__ anchors) {
    const int blk = blockIdx.x;
    const int b = blk / 5, l = blk % 5;
    const int n = c_lvl_n[l], off = c_lvl_off[l], k = c_lvl_k[l];
    const float* row = obj + (size_t)b * A_TOTAL + off;

    __shared__ unsigned int hist[2048];
    __shared__ unsigned int wsum[32];
    __shared__ int sh_bin;
    __shared__ int cntL, cntT;
    __shared__ unsigned long long skey[4096];

    for (int i = threadIdx.x; i < 2048; i += 1024) hist[i] = d_hist[blk][i];
    for (int i = threadIdx.x; i < 4096; i += 1024) skey[i] = ~0ULL;
    if (threadIdx.x == 0) { cntL = 0; cntT = 0; sh_bin = 1 << 29; }
    __syncthreads();

    if (k < n) {
        const int wid = threadIdx.x >> 5, lane2 = threadIdx.x & 31;
        {
            unsigned int s = hist[wid * 64 + lane2] + hist[wid * 64 + 32 + lane2];
#pragma unroll
            for (int d = 16; d > 0; d >>= 1) s += __shfl_down_sync(0xffffffffu, s, d);
            if (lane2 == 0) wsum[wid] = s;
        }
        __syncthreads();
        if (threadIdx.x == 0) {
            unsigned int cum = 0; int g = 0;
            while (g < 32 && cum + wsum[g] < (unsigned int)k) { cum += wsum[g]; g++; }
            int bin = g * 64;
            while (cum + hist[bin] < (unsigned int)k) { cum += hist[bin]; bin++; }
            sh_bin = bin;
        }
        __syncthreads();
    }
    const int bin = sh_bin;

    for (int i = threadIdx.x; i < n; i += 1024) {
        const unsigned long long key =
            ((unsigned long long)fkey_desc(row[i]) << 32) | (unsigned int)i;
        const int hb = (int)(key >> 53);
        if (hb < bin) {
            int p = atomicAdd(&cntL, 1);
            if (p < 2048) skey[p] = key;
        } else if (hb == bin) {
            int p = atomicAdd(&cntT, 1);
            if (p < 2048) skey[2048 + p] = key;
        }
    }
    __syncthreads();

    // bitonic sort 4096 ascending (=> logit desc, idx asc)
    for (int size = 2; size <= 4096; size <<= 1) {
        for (int stride = size >> 1; stride > 0; stride >>= 1) {
            for (int t = threadIdx.x; t < 2048; t += 1024) {
                const int i = ((t / stride) * (stride << 1)) + (t & (stride - 1));
                const int j = i + stride;
                const bool asc = ((i & size) == 0);
                unsigned long long a = skey[i], bb = skey[j];
                if (asc ? (a > bb) : (a < bb)) { skey[i] = bb; skey[j] = a; }
            }
            __syncthreads();
        }
    }

    // ---- fused decode epilogue (identical arithmetic to the reference) ----
    const int r = threadIdx.x;
    if (r < k) {
        const int pos = l * 1000 + r;
        const unsigned long long key = skey[r];
        const unsigned int idx = (unsigned int)key;
        const int a = c_lvl_off[l] + (int)idx;

        const float logit = obj[(size_t)b * A_TOTAL + a];
        const float4 an = *(const float4*)(anchors + (size_t)a * 4);
        const float4 dl = *(const float4*)(deltas + ((size_t)b * A_TOTAL + a) * 4);

        const float BBOX_CLIP = (float)4.135166556742356;

        const float wa = __fsub_rn(an.z, an.x);
        const float ha = __fsub_rn(an.w, an.y);
        const float cxa = __fadd_rn(an.x, __fmul_rn(0.5f, wa));
        const float cya = __fadd_rn(an.y, __fmul_rn(0.5f, ha));

        const float dx = dl.x, dy = dl.y;
        const float dw = fminf(dl.z, BBOX_CLIP);
        const float dh = fminf(dl.w, BBOX_CLIP);

        const float cx = __fadd_rn(__fmul_rn(dx, wa), cxa);
        const float cy = __fadd_rn(__fmul_rn(dy, ha), cya);
        const float w = __fmul_rn(expf(dw), wa);
        const float h = __fmul_rn(expf(dh), ha);

        const float hw = __fmul_rn(0.5f, w);
        const float hh = __fmul_rn(0.5f, h);
        float x1 = __fsub_rn(cx, hw);
        float y1 = __fsub_rn(cy, hh);
        float x2 = __fadd_rn(cx, hw);
        float y2 = __fadd_rn(cy, hh);

        x1 = fminf(fmaxf(x1, 0.0f), 800.0f);
        y1 = fminf(fmaxf(y1, 0.0f), 800.0f);
        x2 = fminf(fmaxf(x2, 0.0f), 800.0f);
        y2 = fminf(fmaxf(y2, 0.0f), 800.0f);

        const float sig = __fdiv_rn(1.0f, __fadd_rn(1.0f, expf(-logit)));

        const bool valid = (__fsub_rn(x2, x1) >= 0.001f) &&
                           (__fsub_rn(y2, y1) >= 0.001f) &&
                           (sig >= 0.0f);

        d_cand_box[b][pos][0] = x1;
        d_cand_box[b][pos][1] = y1;
        d_cand_box[b][pos][2] = x2;
        d_cand_box[b][pos][3] = y2;
        d_cand_sig[b][pos] = sig;
        d_cand_valid[b][pos] = valid ? 1 : 0;

        const float sigp = valid ? sig : __int_as_float(0xff800000); // -inf
        d_sortbuf[b][pos] = ((unsigned long long)fkey_desc(sigp) << 32) | (unsigned int)pos;
    }
}

// ---------------------------------------------------------------------------
// Bitonic sort of d_sortbuf[b][8192], split across 16 blocks + global stages
// ---------------------------------------------------------------------------
__global__ void k_sortA() {   // local: sizes 2..2048
    __shared__ unsigned long long sk[2048];
    const int c = blockIdx.x;
    const int b = c >> 2, chunk = c & 3;
    unsigned long long* src = d_sortbuf[b] + chunk * 2048;
    for (int i = threadIdx.x; i < 2048; i += 1024) sk[i] = src[i];
    __syncthreads();
    const int gbase = chunk * 2048;
    for (int size = 2; size <= 2048; size <<= 1) {
        for (int stride = size >> 1; stride > 0; stride >>= 1) {
            const int t = threadIdx.x;
            const int i = ((t / stride) * (stride << 1)) + (t & (stride - 1));
            const int j = i + stride;
            const bool asc = (((gbase + i) & size) == 0);
            unsigned long long a = sk[i], bb = sk[j];
            if (asc ? (a > bb) : (a < bb)) { sk[i] = bb; sk[j] = a; }
            __syncthreads();
        }
    }
    for (int i = threadIdx.x; i < 2048; i += 1024) src[i] = sk[i];
}

__global__ void k_sortG(int size, int stride) {   // global cross-chunk stage
    const int t = blockIdx.x * blockDim.x + threadIdx.x;   // B*4096
    const int b = t >> 12, w = t & 4095;
    const int i = ((w / stride) * (stride << 1)) + (w & (stride - 1));
    const int j = i + stride;
    const bool asc = ((i & size) == 0);
    unsigned long long a = d_sortbuf[b][i], bb = d_sortbuf[b][j];
    if (asc ? (a > bb) : (a < bb)) { d_sortbuf[b][i] = bb; d_sortbuf[b][j] = a; }
}

__global__ void k_sortL(int size, int write_pos) {   // local tail: strides<=1024
    __shared__ unsigned long long sk[2048];
    const int c = blockIdx.x;
    const int b = c >> 2, chunk = c & 3;
    unsigned long long* src = d_sortbuf[b] + chunk * 2048;
    for (int i = threadIdx.x; i < 2048; i += 1024) sk[i] = src[i];
    __syncthreads();
    const int gbase = chunk * 2048;
    const bool asc = ((gbase & size) == 0);
    for (int stride = 1024; stride > 0; stride >>= 1) {
        const int t = threadIdx.x;
        const int i = ((t / stride) * (stride << 1)) + (t & (stride - 1));
        const int j = i + stride;
        unsigned long long a = sk[i], bb = sk[j];
        if (asc ? (a > bb) : (a < bb)) { sk[i] = bb; sk[j] = a; }
        __syncthreads();
    }
    if (!write_pos) {
        for (int i = threadIdx.x; i < 2048; i += 1024) src[i] = sk[i];
    } else {
        for (int i = threadIdx.x; i < 2048; i += 1024) {
            const int g = gbase + i;
            if (g < KCAND) d_sorted_pos[b][g] = (unsigned int)sk[i];
        }
    }
}

// ---------------------------------------------------------------------------
// iou(i,j) > 0.7 — exact, division-free fast path (band test)
// ---------------------------------------------------------------------------
__device__ __forceinline__ bool iou_gt(const float4 bi, const float ai,
                                       const float4 bj, const float aj) {
    const float xx1 = fmaxf(bi.x, bj.x);
    const float yy1 = fmaxf(bi.y, bj.y);
    const float xx2 = fminf(bi.z, bj.z);
    const float yy2 = fminf(bi.w, bj.w);
    const float ww = fmaxf(__fsub_rn(xx2, xx1), 0.0f);
    const float hh = fmaxf(__fsub_rn(yy2, yy1), 0.0f);
    const float inter = __fmul_rn(ww, hh);
    const float uni = __fsub_rn(__fadd_rn(ai, aj), inter);
    // certainly-true: inter/uni >= 0.7002*(1-eps) > 0.7f after rn-division
    if (inter >= __fmul_rn(0.7002f, uni)) return inter > 0.0f;
    // certainly-false: inter/uni <= 0.6998*(1+eps) < 0.7f after rn-division
    if (inter <= __fmul_rn(0.6998f, uni)) return false;
    return __fdiv_rn(inter, uni) > 0.7f;   // rare borderline band: exact
}

// ---------------------------------------------------------------------------
// K4a: suppression bitmatrix build, upper-triangle words only.
// ---------------------------------------------------------------------------
#define BUILD_SMEM (16000 + 4000)
__global__ void k_nms_build() {
    extern __shared__ unsigned char dynb[];
    float4* sbox = (float4*)dynb;            // [1000]
    float*  sar  = (float*)(dynb + 16000);   // [1000]

    const int blk = blockIdx.x;
    const int group = blk / NCH, chunk = blk % NCH;
    const int b = group / 5, l = group % 5;
    const int k = c_lvl_k[l];
    const int cbase = l * 1000;
    const float loff = (float)l * 1000.0f;

    for (int r = threadIdx.x; r < k; r += blockDim.x) {
        const int pos = cbase + r;
        const float ox1 = __fadd_rn(d_cand_box[b][pos][0], loff);
        const float oy1 = __fadd_rn(d_cand_box[b][pos][1], loff);
        const float ox2 = __fadd_rn(d_cand_box[b][pos][2], loff);
        const float oy2 = __fadd_rn(d_cand_box[b][pos][3], loff);
        sbox[r] = make_float4(ox1, oy1, ox2, oy2);
        sar[r] = __fmul_rn(__fsub_rn(ox2, ox1), __fsub_rn(oy2, oy1));
    }
    __syncthreads();

    const int wid = threadIdx.x >> 5, lane = threadIdx.x & 31;
    const int nwarps = blockDim.x >> 5;
    const int nrows = (k - chunk + NCH - 1) / NCH;
    const int ntasks = nrows * 16;
    for (int t = wid; t < ntasks; t += nwarps) {
        const int r = chunk + (t >> 4) * NCH;   // warp-uniform
        const int w = t & 15;
        if (w < (r >> 6)) continue;             // sub-diagonal: never read
        unsigned long long word = 0ULL;
        if ((w << 6) + 63 > r) {
            const float4 bi = sbox[r];
            const float ai = sar[r];
            const int j1 = (w << 6) + lane;
            const int j2 = j1 + 32;
            bool v1 = false, v2 = false;
            if (j1 > r && j1 < k) v1 = iou_gt(bi, ai, sbox[j1], sar[j1]);
            if (j2 > r && j2 < k) v2 = iou_gt(bi, ai, sbox[j2], sar[j2]);
            const unsigned int lo = __ballot_sync(0xffffffffu, v1);
            const unsigned int hi = __ballot_sync(0xffffffffu, v2);
            word = (unsigned long long)lo | ((unsigned long long)hi << 32);
        }
        if (lane == 0) d_mat[group][r * 16 + w] = word;
    }
}

// ---------------------------------------------------------------------------
// K4b: greedy scan exploiting sparsity. 20 blocks.
// dyn smem: smat u64[16000] | ball u32[32] | remw u64[16] | rowNZ u64[16]
// ---------------------------------------------------------------------------
#define SCAN_SMEM (128000 + 128 + 128 + 128)
__global__ void k_nms_scan() {
    extern __shared__ unsigned char dyns[];
    unsigned long long* smat = (unsigned long long*)dyns;               // [16000]
    unsigned int* ball = (unsigned int*)(dyns + 128000);                // [32]
    unsigned long long* remw = (unsigned long long*)(dyns + 128128);    // [16]
    unsigned long long* rowNZ = (unsigned long long*)(dyns + 128256);   // [16]

    const int group = blockIdx.x;
    const int b = group / 5, l = group % 5;
    const int k = c_lvl_k[l];
    const int cbase = l * 1000;
    const int tid = threadIdx.x;

    if (tid < 16) rowNZ[tid] = 0ULL;
    __syncthreads();

    const int nwords = k * 16;
    for (int i = tid; i < nwords; i += 1024) {
        const unsigned long long v = d_mat[group][i];
        smat[i] = v;
        const int r = i >> 4, w = i & 15;
        if (v != 0ULL && w >= (r >> 6))
            atomicOr(&rowNZ[r >> 6], 1ULL << (r & 63));
    }

    int valid_flag = (tid < k) ? d_cand_valid[b][cbase + tid] : 0;
    const unsigned int bal = __ballot_sync(0xffffffffu, valid_flag);
    if ((tid & 31) == 0) ball[tid >> 5] = bal;
    __syncthreads();

    if (tid < 32) {
        const int lane = tid;
        unsigned long long removed = ~0ULL;
        if (lane < 16) {
            const unsigned long long lo = ball[lane * 2];
            const unsigned long long hi = ball[lane * 2 + 1];
            removed = ~(lo | (hi << 32));
        }
        const int nw = (k + 63) >> 6;
        for (int w = 0; w < nw; w++) {
            const unsigned long long rw0 = __shfl_sync(0xffffffffu, removed, w);
            unsigned long long live0 = ~rw0;
            if (!live0) continue;

            const int r0 = (w << 6) + lane;
            const int r1 = r0 + 32;
            const unsigned long long m0 = (r0 < k) ? smat[(r0 << 4) + w] : 0ULL;
            const unsigned long long m1 = (r1 < k) ? smat[(r1 << 4) + w] : 0ULL;
            const unsigned int nzlo = __ballot_sync(0xffffffffu, m0 != 0ULL);
            const unsigned int nzhi = __ballot_sync(0xffffffffu, m1 != 0ULL);
            const unsigned long long nz =
                (unsigned long long)nzlo | ((unsigned long long)nzhi << 32);

            unsigned long long rm = rw0;
            unsigned long long ser = live0 & nz;
            while (ser) {
                const int bit = __ffsll((long long)ser) - 1;
                ser &= ser - 1ULL;
                if (!((rm >> bit) & 1ULL)) {
                    const unsigned long long mb = __shfl_sync(
                        0xffffffffu, (bit < 32) ? m0 : m1, bit & 31);
                    rm |= mb;
                    ser &= ~rm;
                }
            }
            const unsigned long long kept = live0 & ~rm;
            if (lane == w) removed = rm;

            unsigned long long it = kept & rowNZ[w];
            while (it) {
                const int i = __ffsll((long long)it) - 1;
                it &= it - 1ULL;
                if (lane > w && lane < 16)
                    removed |= smat[(((w << 6) + i) << 4) + lane];
            }
        }
        if (lane < 16) remw[lane] = removed;
    }
    __syncthreads();

    if (tid < k) {
        const int kp = !((remw[tid >> 6] >> (tid & 63)) & 1ULL);
        d_keep[b][cbase + tid] = (unsigned char)kp;
    }
}

// ---------------------------------------------------------------------------
// K5: per-batch rank assignment + output
// ---------------------------------------------------------------------------
__global__ void k_out(float* __restrict__ out) {
    __shared__ unsigned int spos[KCAND];
    __shared__ unsigned char skp[KCAND];
    const int b = blockIdx.x;
    float* ob = out + (size_t)b * POST_NMS * 5;
    for (int i = threadIdx.x; i < POST_NMS * 5; i += blockDim.x) ob[i] = 0.0f;
    for (int i = threadIdx.x; i < KCAND; i += blockDim.x) {
        const unsigned int p = d_sorted_pos[b][i];
        spos[i] = p;
        skp[i] = d_keep[b][p];
    }
    __syncthreads();

    if (threadIdx.x < 32) {
        const int lane = threadIdx.x;
        int rank = 0;
        for (int base = 0; base < KCAND; base += 32) {
            const int i = base + lane;
            const int kpv = (i < KCAND) ? skp[i] : 0;
            const unsigned int mask = __ballot_sync(0xffffffffu, kpv);
            const int myrank = rank + __popc(mask & ((1u << lane) - 1u));
            if (kpv && myrank < POST_NMS) {
                const int pos = (int)spos[i];
                const float4 bx = *(const float4*)&d_cand_box[b][pos][0];
                float* rrow = ob + (size_t)myrank * 5;
                rrow[0] = bx.x; rrow[1] = bx.y; rrow[2] = bx.z; rrow[3] = bx.w;
                rrow[4] = d_cand_sig[b][pos];
            }
            rank += __popc(mask);
            if (rank >= POST_NMS) break;
        }
    }
}

// ---------------------------------------------------------------------------
extern "C" void kernel_launch(void* const* d_in, const int* in_sizes, int n_in,
                              void* d_out, int out_size) {
    const float* obj = (const float*)d_in[0];
    const float* deltas = (const float*)d_in[1];
    const float* anchors = (const float*)d_in[2];
    float* out = (float*)d_out;

    static void* hist_addr = nullptr;
    static void* sortbuf_addr = nullptr;
    if (!hist_addr) {
        cudaGetSymbolAddress(&hist_addr, d_hist);
        cudaGetSymbolAddress(&sortbuf_addr, d_sortbuf);
        cudaFuncSetAttribute(k_nms_scan, cudaFuncAttributeMaxDynamicSharedMemorySize,
                             SCAN_SMEM);
    }

    cudaMemsetAsync(hist_addr, 0, sizeof(unsigned int) * B * 5 * 2048);
    cudaMemsetAsync(sortbuf_addr, 0xFF, sizeof(unsigned long long) * B * 8192);

    k_hist<<<B * 5 * HCH, 512>>>(obj);
    k_topk<<<B * 5, 1024>>>(obj, deltas, anchors);

    k_nms_build<<<B * 5 * NCH, 512, BUILD_SMEM>>>();
    k_nms_scan<<<B * 5, 1024, SCAN_SMEM>>>();

    // bitonic 8192 per batch, 16-block local + global cross-chunk stages
    k_sortA<<<16, 1024>>>();
    k_sortG<<<64, 256>>>(4096, 2048);
    k_sortL<<<16, 1024>>>(4096, 0);
    k_sortG<<<64, 256>>>(8192, 4096);
    k_sortG<<<64, 256>>>(8192, 2048);
    k_sortL<<<16, 1024>>>(8192, 1);

    k_out<<<B, 1024>>>(out);
}

// round 16
// speedup vs baseline: 4.3044x; 1.1028x over previous
#include <cuda_runtime.h>
#include <cuda_bf16.h>
#include <math.h>

#define B 4
#define A_TOTAL 159882
#define KCAND 4507
#define POST_NMS 1000
#define NCH 28
#define HCH 8

__constant__ int c_lvl_n[5]   = {120000, 30000, 7500, 1875, 507};
__constant__ int c_lvl_off[5] = {0, 120000, 150000, 157500, 159375};
__constant__ int c_lvl_k[5]   = {1000, 1000, 1000, 1000, 507};

// static scratch (no allocation allowed)
__device__ unsigned int       d_hist[B * 5][2048];
__device__ float              d_cand_box[B][KCAND][4];
__device__ float              d_cand_sig[B][KCAND];
__device__ unsigned char      d_cand_valid[B][KCAND];
__device__ unsigned long long d_lvlkey[B * 5][1024];   // partitioned, key-ascending
__device__ unsigned int       d_sorted_pos[B][KCAND];
__device__ unsigned char      d_keep[B][KCAND];
__device__ unsigned long long d_mat[B * 5][16000];     // suppression bitmatrix

// monotone float -> u32 (ascending), then inverted for descending sort keys
__device__ __forceinline__ unsigned int fkey_desc(float f) {
    unsigned int b = __float_as_uint(f);
    unsigned int o = (b & 0x80000000u) ? ~b : (b | 0x80000000u);
    return ~o;
}

// ---------------------------------------------------------------------------
// K0: partial histograms (warp-aggregated global atomics), 160 blocks
// ---------------------------------------------------------------------------
__global__ void k_hist(const float* __restrict__ obj) {
    const int blk = blockIdx.x;
    const int group = blk / HCH, chunk = blk % HCH;
    const int b = group / 5, l = group % 5;
    const int n = c_lvl_n[l], off = c_lvl_off[l], k = c_lvl_k[l];
    if (k >= n) return;
    const float* row = obj + (size_t)b * A_TOTAL + off;
    const int slice = (n + HCH - 1) / HCH;
    const int lo = chunk * slice;
    const int hi = min(n, lo + slice);
    const int lane = threadIdx.x & 31;
    for (int base = lo; base < hi; base += blockDim.x) {
        const int i = base + threadIdx.x;
        const unsigned int active = __ballot_sync(0xffffffffu, i < hi);
        if (i < hi) {
            const unsigned int bin = fkey_desc(row[i]) >> 21;
            const unsigned int mm = __match_any_sync(active, bin);
            if (lane == (__ffs(mm) - 1))
                atomicAdd(&d_hist[group][bin], (unsigned int)__popc(mm));
        }
    }
}

// ---------------------------------------------------------------------------
// K1: per-(batch,level) exact top-k (bin select + compact + bitonic 4096)
//     + fused decode epilogue + stable valid-partition into d_lvlkey.
// ---------------------------------------------------------------------------
__global__ void k_topk(const float* __restrict__ obj,
                       const float* __restrict__ deltas,
                       const float* __restrict__ anchors) {
    const int blk = blockIdx.x;
    const int b = blk / 5, l = blk % 5;
    const int n = c_lvl_n[l], off = c_lvl_off[l], k = c_lvl_k[l];
    const float* row = obj + (size_t)b * A_TOTAL + off;

    __shared__ unsigned int hist[2048];
    __shared__ unsigned int wsum[32];
    __shared__ int sh_bin;
    __shared__ int cntL, cntT;
    __shared__ unsigned long long skey[4096];
    __shared__ unsigned int wpre[32];
    __shared__ unsigned int sh_totv;

    for (int i = threadIdx.x; i < 2048; i += 1024) hist[i] = d_hist[blk][i];
    for (int i = threadIdx.x; i < 4096; i += 1024) skey[i] = ~0ULL;
    if (threadIdx.x == 0) { cntL = 0; cntT = 0; sh_bin = 1 << 29; }
    __syncthreads();

    if (k < n) {
        const int wid = threadIdx.x >> 5, lane2 = threadIdx.x & 31;
        {
            unsigned int s = hist[wid * 64 + lane2] + hist[wid * 64 + 32 + lane2];
#pragma unroll
            for (int d = 16; d > 0; d >>= 1) s += __shfl_down_sync(0xffffffffu, s, d);
            if (lane2 == 0) wsum[wid] = s;
        }
        __syncthreads();
        if (threadIdx.x == 0) {
            unsigned int cum = 0; int g = 0;
            while (g < 32 && cum + wsum[g] < (unsigned int)k) { cum += wsum[g]; g++; }
            int bin = g * 64;
            while (cum + hist[bin] < (unsigned int)k) { cum += hist[bin]; bin++; }
            sh_bin = bin;
        }
        __syncthreads();
    }
    const int bin = sh_bin;

    for (int i = threadIdx.x; i < n; i += 1024) {
        const unsigned long long key =
            ((unsigned long long)fkey_desc(row[i]) << 32) | (unsigned int)i;
        const int hb = (int)(key >> 53);
        if (hb < bin) {
            int p = atomicAdd(&cntL, 1);
            if (p < 2048) skey[p] = key;
        } else if (hb == bin) {
            int p = atomicAdd(&cntT, 1);
            if (p < 2048) skey[2048 + p] = key;
        }
    }
    __syncthreads();

    // bitonic sort 4096 ascending (=> logit desc, idx asc)
    for (int size = 2; size <= 4096; size <<= 1) {
        for (int stride = size >> 1; stride > 0; stride >>= 1) {
            for (int t = threadIdx.x; t < 2048; t += 1024) {
                const int i = ((t / stride) * (stride << 1)) + (t & (stride - 1));
                const int j = i + stride;
                const bool asc = ((i & size) == 0);
                unsigned long long a = skey[i], bb = skey[j];
                if (asc ? (a > bb) : (a < bb)) { skey[i] = bb; skey[j] = a; }
            }
            __syncthreads();
        }
    }

    // ---- fused decode epilogue (identical arithmetic to the reference) ----
    const int r = threadIdx.x;
    bool vflag = false;
    unsigned long long keyOut = 0ULL;
    if (r < k) {
        const int pos = l * 1000 + r;
        const unsigned long long key = skey[r];
        const unsigned int idx = (unsigned int)key;
        const int a = c_lvl_off[l] + (int)idx;

        const float logit = obj[(size_t)b * A_TOTAL + a];
        const float4 an = *(const float4*)(anchors + (size_t)a * 4);
        const float4 dl = *(const float4*)(deltas + ((size_t)b * A_TOTAL + a) * 4);

        const float BBOX_CLIP = (float)4.135166556742356;

        const float wa = __fsub_rn(an.z, an.x);
        const float ha = __fsub_rn(an.w, an.y);
        const float cxa = __fadd_rn(an.x, __fmul_rn(0.5f, wa));
        const float cya = __fadd_rn(an.y, __fmul_rn(0.5f, ha));

        const float dx = dl.x, dy = dl.y;
        const float dw = fminf(dl.z, BBOX_CLIP);
        const float dh = fminf(dl.w, BBOX_CLIP);

        const float cx = __fadd_rn(__fmul_rn(dx, wa), cxa);
        const float cy = __fadd_rn(__fmul_rn(dy, ha), cya);
        const float w = __fmul_rn(expf(dw), wa);
        const float h = __fmul_rn(expf(dh), ha);

        const float hw = __fmul_rn(0.5f, w);
        const float hh = __fmul_rn(0.5f, h);
        float x1 = __fsub_rn(cx, hw);
        float y1 = __fsub_rn(cy, hh);
        float x2 = __fadd_rn(cx, hw);
        float y2 = __fadd_rn(cy, hh);

        x1 = fminf(fmaxf(x1, 0.0f), 800.0f);
        y1 = fminf(fmaxf(y1, 0.0f), 800.0f);
        x2 = fminf(fmaxf(x2, 0.0f), 800.0f);
        y2 = fminf(fmaxf(y2, 0.0f), 800.0f);

        const float sig = __fdiv_rn(1.0f, __fadd_rn(1.0f, expf(-logit)));

        vflag = (__fsub_rn(x2, x1) >= 0.001f) &&
                (__fsub_rn(y2, y1) >= 0.001f) &&
                (sig >= 0.0f);

        d_cand_box[b][pos][0] = x1;
        d_cand_box[b][pos][1] = y1;
        d_cand_box[b][pos][2] = x2;
        d_cand_box[b][pos][3] = y2;
        d_cand_sig[b][pos] = sig;
        d_cand_valid[b][pos] = vflag ? 1 : 0;

        const float sigp = vflag ? sig : __int_as_float(0xff800000); // -inf
        keyOut = ((unsigned long long)fkey_desc(sigp) << 32) | (unsigned int)pos;
    }

    // ---- stable partition (valid first, order preserved) into d_lvlkey ----
    const int wid = r >> 5, lane = r & 31;
    const unsigned int wm = __ballot_sync(0xffffffffu, vflag);
    if (lane == 0) wpre[wid] = __popc(wm);
    __syncthreads();
    if (r < 32) {
        unsigned int v = wpre[r];
        unsigned int x = v;
#pragma unroll
        for (int d = 1; d < 32; d <<= 1) {
            unsigned int y = __shfl_up_sync(0xffffffffu, x, d);
            if (r >= d) x += y;
        }
        wpre[r] = x - v;
        if (r == 31) sh_totv = x;
    }
    __syncthreads();
    if (r < k) {
        const unsigned int pv = wpre[wid] + __popc(wm & ((1u << lane) - 1u));
        const int dst = vflag ? (int)pv : (int)(sh_totv + (unsigned int)r - pv);
        d_lvlkey[blk][dst] = keyOut;
    }
}

// ---------------------------------------------------------------------------
// K3: global rank via 5-way merge of sorted level lists (binary searches)
// ---------------------------------------------------------------------------
__global__ void k_rank() {
    __shared__ unsigned long long sk[5][1024];   // 40KB
    const int b = blockIdx.x;
    const int tid = threadIdx.x;
    for (int i = tid; i < 5 * 1024; i += 1024) {
        const int l = i >> 10, r = i & 1023;
        if (r < c_lvl_k[l]) sk[l][r] = d_lvlkey[b * 5 + l][r];
    }
    __syncthreads();
    for (int i = tid; i < KCAND; i += 1024) {
        const int l = i / 1000;
        const int r = i - l * 1000;
        const unsigned long long key = sk[l][r];
        int rank = r;
#pragma unroll
        for (int l2 = 0; l2 < 5; l2++) {
            if (l2 == l) continue;
            int lo = 0, hi = c_lvl_k[l2];
            while (lo < hi) {
                const int mid = (lo + hi) >> 1;
                if (sk[l2][mid] < key) lo = mid + 1; else hi = mid;
            }
            rank += lo;
        }
        d_sorted_pos[b][rank] = (unsigned int)key;
    }
}

// ---------------------------------------------------------------------------
// iou(i,j) > 0.7 — exact, division-free fast path (band test)
// ---------------------------------------------------------------------------
__device__ __forceinline__ bool iou_gt(const float4 bi, const float ai,
                                       const float4 bj, const float aj) {
    const float xx1 = fmaxf(bi.x, bj.x);
    const float yy1 = fmaxf(bi.y, bj.y);
    const float xx2 = fminf(bi.z, bj.z);
    const float yy2 = fminf(bi.w, bj.w);
    const float ww = fmaxf(__fsub_rn(xx2, xx1), 0.0f);
    const float hh = fmaxf(__fsub_rn(yy2, yy1), 0.0f);
    const float inter = __fmul_rn(ww, hh);
    const float uni = __fsub_rn(__fadd_rn(ai, aj), inter);
    if (inter >= __fmul_rn(0.7002f, uni)) return inter > 0.0f;
    if (inter <= __fmul_rn(0.6998f, uni)) return false;
    return __fdiv_rn(inter, uni) > 0.7f;   // rare borderline band: exact
}

// ---------------------------------------------------------------------------
// K4a: suppression bitmatrix build, upper-triangle words only. 560 blocks.
// ---------------------------------------------------------------------------
#define BUILD_SMEM (16000 + 4000)
__global__ void k_nms_build() {
    extern __shared__ unsigned char dynb[];
    float4* sbox = (float4*)dynb;            // [1000]
    float*  sar  = (float*)(dynb + 16000);   // [1000]

    const int blk = blockIdx.x;
    const int group = blk / NCH, chunk = blk % NCH;
    const int b = group / 5, l = group % 5;
    const int k = c_lvl_k[l];
    const int cbase = l * 1000;
    const float loff = (float)l * 1000.0f;

    for (int r = threadIdx.x; r < k; r += blockDim.x) {
        const int pos = cbase + r;
        const float ox1 = __fadd_rn(d_cand_box[b][pos][0], loff);
        const float oy1 = __fadd_rn(d_cand_box[b][pos][1], loff);
        const float ox2 = __fadd_rn(d_cand_box[b][pos][2], loff);
        const float oy2 = __fadd_rn(d_cand_box[b][pos][3], loff);
        sbox[r] = make_float4(ox1, oy1, ox2, oy2);
        sar[r] = __fmul_rn(__fsub_rn(ox2, ox1), __fsub_rn(oy2, oy1));
    }
    __syncthreads();

    const int wid = threadIdx.x >> 5, lane = threadIdx.x & 31;
    const int nwarps = blockDim.x >> 5;
    const int nrows = (k - chunk + NCH - 1) / NCH;
    const int ntasks = nrows * 16;
    for (int t = wid; t < ntasks; t += nwarps) {
        const int r = chunk + (t >> 4) * NCH;   // warp-uniform
        const int w = t & 15;
        if (w < (r >> 6)) continue;             // sub-diagonal: never read
        unsigned long long word = 0ULL;
        if ((w << 6) + 63 > r) {
            const float4 bi = sbox[r];
            const float ai = sar[r];
            const int j1 = (w << 6) + lane;
            const int j2 = j1 + 32;
            bool v1 = false, v2 = false;
            if (j1 > r && j1 < k) v1 = iou_gt(bi, ai, sbox[j1], sar[j1]);
            if (j2 > r && j2 < k) v2 = iou_gt(bi, ai, sbox[j2], sar[j2]);
            const unsigned int lo = __ballot_sync(0xffffffffu, v1);
            const unsigned int hi = __ballot_sync(0xffffffffu, v2);
            word = (unsigned long long)lo | ((unsigned long long)hi << 32);
        }
        if (lane == 0) d_mat[group][r * 16 + w] = word;
    }
}

// ---------------------------------------------------------------------------
// K4b: greedy scan exploiting sparsity. 20 blocks.
// dyn smem: smat u64[16000] | ball u32[32] | remw u64[16] | rowNZ u64[16]
// ---------------------------------------------------------------------------
#define SCAN_SMEM (128000 + 128 + 128 + 128)
__global__ void k_nms_scan() {
    extern __shared__ unsigned char dyns[];
    unsigned long long* smat = (unsigned long long*)dyns;               // [16000]
    unsigned int* ball = (unsigned int*)(dyns + 128000);                // [32]
    unsigned long long* remw = (unsigned long long*)(dyns + 128128);    // [16]
    unsigned long long* rowNZ = (unsigned long long*)(dyns + 128256);   // [16]

    const int group = blockIdx.x;
    const int b = group / 5, l = group % 5;
    const int k = c_lvl_k[l];
    const int cbase = l * 1000;
    const int tid = threadIdx.x;

    if (tid < 16) rowNZ[tid] = 0ULL;
    __syncthreads();

    const int nwords = k * 16;
    for (int i = tid; i < nwords; i += 1024) {
        const unsigned long long v = d_mat[group][i];
        smat[i] = v;
        const int r = i >> 4, w = i & 15;
        if (v != 0ULL && w >= (r >> 6))
            atomicOr(&rowNZ[r >> 6], 1ULL << (r & 63));
    }

    int valid_flag = (tid < k) ? d_cand_valid[b][cbase + tid] : 0;
    const unsigned int bal = __ballot_sync(0xffffffffu, valid_flag);
    if ((tid & 31) == 0) ball[tid >> 5] = bal;
    __syncthreads();

    if (tid < 32) {
        const int lane = tid;
        unsigned long long removed = ~0ULL;
        if (lane < 16) {
            const unsigned long long lo = ball[lane * 2];
            const unsigned long long hi = ball[lane * 2 + 1];
            removed = ~(lo | (hi << 32));
        }
        const int nw = (k + 63) >> 6;
        for (int w = 0; w < nw; w++) {
            const unsigned long long rw0 = __shfl_sync(0xffffffffu, removed, w);
            unsigned long long live0 = ~rw0;
            if (!live0) continue;

            const int r0 = (w << 6) + lane;
            const int r1 = r0 + 32;
            const unsigned long long m0 = (r0 < k) ? smat[(r0 << 4) + w] : 0ULL;
            const unsigned long long m1 = (r1 < k) ? smat[(r1 << 4) + w] : 0ULL;
            const unsigned int nzlo = __ballot_sync(0xffffffffu, m0 != 0ULL);
            const unsigned int nzhi = __ballot_sync(0xffffffffu, m1 != 0ULL);
            const unsigned long long nz =
                (unsigned long long)nzlo | ((unsigned long long)nzhi << 32);

            unsigned long long rm = rw0;
            unsigned long long ser = live0 & nz;
            while (ser) {
                const int bit = __ffsll((long long)ser) - 1;
                ser &= ser - 1ULL;
                if (!((rm >> bit) & 1ULL)) {
                    const unsigned long long mb = __shfl_sync(
                        0xffffffffu, (bit < 32) ? m0 : m1, bit & 31);
                    rm |= mb;
                    ser &= ~rm;
                }
            }
            const unsigned long long kept = live0 & ~rm;
            if (lane == w) removed = rm;

            unsigned long long it = kept & rowNZ[w];
            while (it) {
                const int i = __ffsll((long long)it) - 1;
                it &= it - 1ULL;
                if (lane > w && lane < 16)
                    removed |= smat[(((w << 6) + i) << 4) + lane];
            }
        }
        if (lane < 16) remw[lane] = removed;
    }
    __syncthreads();

    if (tid < k) {
        const int kp = !((remw[tid >> 6] >> (tid & 63)) & 1ULL);
        d_keep[b][cbase + tid] = (unsigned char)kp;
    }
}

// ---------------------------------------------------------------------------
// K5: per-batch rank assignment + output
// ---------------------------------------------------------------------------
__global__ void k_out(float* __restrict__ out) {
    __shared__ unsigned int spos[KCAND];
    __shared__ unsigned char skp[KCAND];
    const int b = blockIdx.x;
    float* ob = out + (size_t)b * POST_NMS * 5;
    for (int i = threadIdx.x; i < POST_NMS * 5; i += blockDim.x) ob[i] = 0.0f;
    for (int i = threadIdx.x; i < KCAND; i += blockDim.x) {
        const unsigned int p = d_sorted_pos[b][i];
        spos[i] = p;
        skp[i] = d_keep[b][p];
    }
    __syncthreads();

    if (threadIdx.x < 32) {
        const int lane = threadIdx.x;
        int rank = 0;
        for (int base = 0; base < KCAND; base += 32) {
            const int i = base + lane;
            const int kpv = (i < KCAND) ? skp[i] : 0;
            const unsigned int mask = __ballot_sync(0xffffffffu, kpv);
            const int myrank = rank + __popc(mask & ((1u << lane) - 1u));
            if (kpv && myrank < POST_NMS) {
                const int pos = (int)spos[i];
                const float4 bx = *(const float4*)&d_cand_box[b][pos][0];
                float* rrow = ob + (size_t)myrank * 5;
                rrow[0] = bx.x; rrow[1] = bx.y; rrow[2] = bx.z; rrow[3] = bx.w;
                rrow[4] = d_cand_sig[b][pos];
            }
            rank += __popc(mask);
            if (rank >= POST_NMS) break;
        }
    }
}

// ---------------------------------------------------------------------------
extern "C" void kernel_launch(void* const* d_in, const int* in_sizes, int n_in,
                              void* d_out, int out_size) {
    const float* obj = (const float*)d_in[0];
    const float* deltas = (const float*)d_in[1];
    const float* anchors = (const float*)d_in[2];
    float* out = (float*)d_out;

    static void* hist_addr = nullptr;
    if (!hist_addr) {
        cudaGetSymbolAddress(&hist_addr, d_hist);
        cudaFuncSetAttribute(k_nms_scan, cudaFuncAttributeMaxDynamicSharedMemorySize,
                             SCAN_SMEM);
    }

    cudaMemsetAsync(hist_addr, 0, sizeof(unsigned int) * B * 5 * 2048);

    k_hist<<<B * 5 * HCH, 512>>>(obj);
    k_topk<<<B * 5, 1024>>>(obj, deltas, anchors);

    k_nms_build<<<B * 5 * NCH, 512, BUILD_SMEM>>>();
    k_nms_scan<<<B * 5, 1024, SCAN_SMEM>>>();

    k_rank<<<B, 1024>>>();
    k_out<<<B, 1024>>>(out);
}